// round 15
// baseline (speedup 1.0000x reference)
#include <cuda_runtime.h>
#include <cuda_bf16.h>
#include <cstdint>
#include <cstddef>

// Problem dims
#define B_   16
#define H_   384
#define G4   1536          // 4*H
#define G8   3072          // both dirs
#define M_   16384         // B*S
#define S_   1024
#define K2   2304          // split-GEMM K'' = 3*768

// ---------------- scratch ----------------
__device__ __align__(256) float g_xpAll [(size_t)M_ * G8];
__device__ __align__(256) float g_lstm  [(size_t)M_ * 768];
__device__ __align__(256) float g_hcat  [(size_t)M_ * 768];
__device__ __align__(256) float g_h2    [(size_t)M_ * H_];
__device__ __align__(256) float g_mlp1  [(size_t)M_ * 256];
__device__ __align__(256) float g_mlp2  [(size_t)M_ * 96];
__device__ __align__(256) __nv_bfloat16 g_A2 [(size_t)M_ * K2];
__device__ __align__(256) __nv_bfloat16 g_W2 [(size_t)G8 * K2];
__device__ __align__(256) __nv_bfloat16 g_Wfc[(size_t)H_ * K2];
__device__ __align__(256) unsigned g_cnt[256 * 8];

// ---------------- packed f32x2 helpers ----------------
__device__ __forceinline__ void fma2_(unsigned long long& d,
                                      unsigned long long a,
                                      unsigned long long b) {
    asm("fma.rn.f32x2 %0, %1, %2, %0;" : "+l"(d) : "l"(a), "l"(b));
}
__device__ __forceinline__ unsigned long long pack2_(float x, float y) {
    unsigned long long d;
    asm("mov.b64 %0, {%1, %2};" : "=l"(d) : "f"(x), "f"(y));
    return d;
}
__device__ __forceinline__ float2 unpack2_(unsigned long long v) {
    float2 r;
    asm("mov.b64 {%0, %1}, %2;" : "=f"(r.x), "=f"(r.y) : "l"(v));
    return r;
}

// ---------------- generic SIMT GEMM (MLP head) ----------------
template<int ACT>
__global__ __launch_bounds__(256, 2) void gemm_bias_kernel(
    const float* __restrict__ A, const float* __restrict__ W,
    const float* __restrict__ bias, float* __restrict__ C,
    int M, int N, int K, int ldc)
{
    __shared__ float sA[16][132];
    __shared__ float sB[16][132];
    int tid = threadIdx.x;
    int m0 = blockIdx.y * 128;
    int n0 = blockIdx.x * 128;
    int tx = tid & 15, ty = tid >> 4;

    unsigned long long acc2[8][4];
#pragma unroll
    for (int i = 0; i < 8; i++)
#pragma unroll
        for (int j = 0; j < 4; j++) acc2[i][j] = 0ULL;

    for (int k0 = 0; k0 < K; k0 += 16) {
#pragma unroll
        for (int e = 0; e < 2; e++) {
            int f4 = tid + 256 * e;
            int r  = f4 >> 2;
            int c4 = (f4 & 3) << 2;
            float4 av = *(const float4*)(A + (size_t)(m0 + r) * K + k0 + c4);
            sA[c4 + 0][r] = av.x; sA[c4 + 1][r] = av.y;
            sA[c4 + 2][r] = av.z; sA[c4 + 3][r] = av.w;
            int n = n0 + r;
            float4 wv = make_float4(0.f, 0.f, 0.f, 0.f);
            if (n < N) wv = *(const float4*)(W + (size_t)n * K + k0 + c4);
            sB[c4 + 0][r] = wv.x; sB[c4 + 1][r] = wv.y;
            sB[c4 + 2][r] = wv.z; sB[c4 + 3][r] = wv.w;
        }
        __syncthreads();
#pragma unroll
        for (int kk = 0; kk < 16; kk++) {
            float a[8];
            *(float4*)&a[0] = *(const float4*)&sA[kk][ty * 8];
            *(float4*)&a[4] = *(const float4*)&sA[kk][ty * 8 + 4];
            ulonglong2 bv0 = *(const ulonglong2*)&sB[kk][tx * 8];
            ulonglong2 bv1 = *(const ulonglong2*)&sB[kk][tx * 8 + 4];
            unsigned long long b2[4] = {bv0.x, bv0.y, bv1.x, bv1.y};
#pragma unroll
            for (int i = 0; i < 8; i++) {
                unsigned long long a2 = pack2_(a[i], a[i]);
#pragma unroll
                for (int j = 0; j < 4; j++)
                    fma2_(acc2[i][j], a2, b2[j]);
            }
        }
        __syncthreads();
    }

#pragma unroll
    for (int i = 0; i < 8; i++) {
        int m = m0 + ty * 8 + i;
#pragma unroll
        for (int j2 = 0; j2 < 4; j2++) {
            float2 p = unpack2_(acc2[i][j2]);
            int n = n0 + tx * 8 + j2 * 2;
            if (n < N) {
                float v0 = p.x + bias[n];
                if (ACT) v0 = fmaxf(v0, 0.f);
                C[(size_t)m * ldc + n] = v0;
            }
            if (n + 1 < N) {
                float v1 = p.y + bias[n + 1];
                if (ACT) v1 = fmaxf(v1, 0.f);
                C[(size_t)m * ldc + n + 1] = v1;
            }
        }
    }
}

// ---------------- bf16 split prep ----------------
__global__ __launch_bounds__(256) void split_prep_kernel(
    const float* __restrict__ in, __nv_bfloat16* __restrict__ out,
    int nquads, int mode)
{
    int g = blockIdx.x * blockDim.x + threadIdx.x;
    if (g >= nquads) return;
    int m = g / 192;
    int q = (g % 192) * 4;
    float4 v = *(const float4*)(in + (size_t)m * 768 + q);
    float a[4] = {v.x, v.y, v.z, v.w};
    float h0 = __bfloat162float(__float2bfloat16(a[0]));
    float h1 = __bfloat162float(__float2bfloat16(a[1]));
    float h2 = __bfloat162float(__float2bfloat16(a[2]));
    float h3 = __bfloat162float(__float2bfloat16(a[3]));
    __nv_bfloat162 hi01 = __nv_bfloat162(__float2bfloat16(a[0]), __float2bfloat16(a[1]));
    __nv_bfloat162 hi23 = __nv_bfloat162(__float2bfloat16(a[2]), __float2bfloat16(a[3]));
    __nv_bfloat162 lo01 = __nv_bfloat162(__float2bfloat16(a[0] - h0), __float2bfloat16(a[1] - h1));
    __nv_bfloat162 lo23 = __nv_bfloat162(__float2bfloat16(a[2] - h2), __float2bfloat16(a[3] - h3));
    __nv_bfloat16* o = out + (size_t)m * K2 + q;
    *(__nv_bfloat162*)(o + 0) = hi01;  *(__nv_bfloat162*)(o + 2) = hi23;
    if (mode == 0) {
        *(__nv_bfloat162*)(o + 768)  = hi01;  *(__nv_bfloat162*)(o + 770)  = hi23;
        *(__nv_bfloat162*)(o + 1536) = lo01;  *(__nv_bfloat162*)(o + 1538) = lo23;
    } else {
        *(__nv_bfloat162*)(o + 768)  = lo01;  *(__nv_bfloat162*)(o + 770)  = lo23;
        *(__nv_bfloat162*)(o + 1536) = hi01;  *(__nv_bfloat162*)(o + 1538) = hi23;
    }
}

// ---------------- warp-MMA bf16 GEMM ----------------
#define TG_NBLK 36

__device__ __forceinline__ uint32_t smem_u32_(const void* p) {
    uint32_t a;
    asm("{ .reg .u64 t; cvta.to.shared.u64 t, %1; cvt.u32.u64 %0, t; }" : "=r"(a) : "l"(p));
    return a;
}
__device__ __forceinline__ uint32_t swz_(uint32_t off) {
    return off ^ ((off >> 3) & 0x70);
}
__device__ __forceinline__ void cp16_(uint32_t s, const void* g) {
    asm volatile("cp.async.cg.shared.global [%0], [%1], 16;" :: "r"(s), "l"(g) : "memory");
}
#define LDSM4_(d0, d1, d2, d3, addr) \
    asm volatile("ldmatrix.sync.aligned.m8n8.x4.shared.b16 {%0,%1,%2,%3}, [%4];" \
                 : "=r"(d0), "=r"(d1), "=r"(d2), "=r"(d3) : "r"(addr))
#define MMA16816_(c, a, b0, b1) \
    asm volatile("mma.sync.aligned.m16n8k16.row.col.f32.bf16.bf16.f32 " \
                 "{%0,%1,%2,%3}, {%4,%5,%6,%7}, {%8,%9}, {%0,%1,%2,%3};" \
                 : "+f"((c)[0]), "+f"((c)[1]), "+f"((c)[2]), "+f"((c)[3]) \
                 : "r"((a)[0]), "r"((a)[1]), "r"((a)[2]), "r"((a)[3]), \
                   "r"(b0), "r"(b1))

__global__ __launch_bounds__(256) void tgemm_kernel(
    const __nv_bfloat16* __restrict__ A2,
    const __nv_bfloat16* __restrict__ W2,
    const float* __restrict__ biasA,
    const float* __restrict__ biasB,
    int nsplit,
    float* __restrict__ C, int ldc)
{
    extern __shared__ char smraw[];
    uint32_t sb = smem_u32_(smraw);
    int tid  = threadIdx.x;
    int wid  = tid >> 5;
    int lane = tid & 31;
    int n0 = blockIdx.x * 128;
    int m0 = blockIdx.y * 128;
    int wm = (wid & 3) * 32;
    int wn = (wid >> 2) * 64;

    const float* bp = ((int)blockIdx.x < nsplit) ? biasA : biasB;
    int coff = ((int)blockIdx.x < nsplit) ? 0 : nsplit * 128;

    float acc[2][8][4];
#pragma unroll
    for (int mt = 0; mt < 2; mt++)
#pragma unroll
        for (int nt = 0; nt < 8; nt++)
#pragma unroll
            for (int e = 0; e < 4; e++) acc[mt][nt][e] = 0.f;

    int arow = wm + (lane & 15);
    uint32_t arowoff = (uint32_t)arow * 128;
    uint32_t amask   = (uint32_t)(arow & 7) << 4;
    uint32_t akh     = (uint32_t)(lane >> 4) * 16;

    int brow = wn + (lane & 7) + ((lane >> 4) << 3);
    uint32_t browoff = (uint32_t)brow * 128;
    uint32_t bmask   = (uint32_t)(brow & 7) << 4;
    uint32_t bkh     = (uint32_t)((lane >> 3) & 1) * 16;

#pragma unroll
    for (int i = 0; i < 4; i++) {
        int cid = tid + 256 * i;
        int row = cid >> 3, ch = cid & 7;
        uint32_t so = swz_((uint32_t)row * 128 + (uint32_t)ch * 16);
        cp16_(sb + so,           A2 + (size_t)(m0 + row) * K2 + ch * 8);
        cp16_(sb + 32768 + so,   W2 + (size_t)(n0 + row) * K2 + ch * 8);
    }
    asm volatile("cp.async.commit_group;" ::: "memory");

    for (int blk = 0; blk < TG_NBLK; blk++) {
        int bufc = blk & 1;
        if (blk + 1 < TG_NBLK) {
            int bufn = (blk + 1) & 1;
            size_t gk = (size_t)(blk + 1) * 64;
#pragma unroll
            for (int i = 0; i < 4; i++) {
                int cid = tid + 256 * i;
                int row = cid >> 3, ch = cid & 7;
                uint32_t so = swz_((uint32_t)row * 128 + (uint32_t)ch * 16);
                cp16_(sb + bufn * 16384 + so,
                      A2 + (size_t)(m0 + row) * K2 + gk + ch * 8);
                cp16_(sb + 32768 + bufn * 16384 + so,
                      W2 + (size_t)(n0 + row) * K2 + gk + ch * 8);
            }
            asm volatile("cp.async.commit_group;" ::: "memory");
            asm volatile("cp.async.wait_group 1;" ::: "memory");
        } else {
            asm volatile("cp.async.wait_group 0;" ::: "memory");
        }
        __syncthreads();

        uint32_t abuf = sb + bufc * 16384;
        uint32_t bbuf = sb + 32768 + bufc * 16384;
#pragma unroll
        for (int kk = 0; kk < 4; kk++) {
            uint32_t acol = (akh + (uint32_t)kk * 32) ^ amask;
            uint32_t bcol = (bkh + (uint32_t)kk * 32) ^ bmask;
            uint32_t a[2][4], b[4][4];
#pragma unroll
            for (int mt = 0; mt < 2; mt++)
                LDSM4_(a[mt][0], a[mt][1], a[mt][2], a[mt][3],
                       abuf + arowoff + mt * 2048 + acol);
#pragma unroll
            for (int g = 0; g < 4; g++)
                LDSM4_(b[g][0], b[g][1], b[g][2], b[g][3],
                       bbuf + browoff + g * 2048 + bcol);
#pragma unroll
            for (int mt = 0; mt < 2; mt++)
#pragma unroll
                for (int nt = 0; nt < 8; nt++) {
                    int g = nt >> 1, h = (nt & 1) * 2;
                    MMA16816_(acc[mt][nt], a[mt], b[g][h], b[g][h + 1]);
                }
        }
        __syncthreads();
    }

#pragma unroll
    for (int mt = 0; mt < 2; mt++)
#pragma unroll
        for (int nt = 0; nt < 8; nt++) {
            int row = m0 + wm + mt * 16 + (lane >> 2);
            int col = n0 + wn + nt * 8 + (lane & 3) * 2;
            float2 bv = *(const float2*)(bp + (col - coff));
            float2 o0 = make_float2(acc[mt][nt][0] + bv.x, acc[mt][nt][1] + bv.y);
            float2 o1 = make_float2(acc[mt][nt][2] + bv.x, acc[mt][nt][3] + bv.y);
            *(float2*)(C + (size_t)row * ldc + col) = o0;
            *(float2*)(C + (size_t)(row + 8) * ldc + col) = o1;
        }
}

// ---------------- LSTM scan: tensor-core mini-GEMM ----------------
// 64 CTAs = 2 dir x 32 unit-groups; CTA = 16 batches x 48 gate-rows.
// G[16,48] = h[16,384] . Whh[48,384]^T via bf16 hi/lo split (K'=1152) and
// mma.m16n8k16 (patterns identical to tgemm). Warp w owns logical k-slice
// [144w,144w+144): polls its 12 producers, stages+converts h, mma's, stores
// split-k partials (x8); one barrier/step; 192-thread combine.
#define SC_NCTA 64
#define SC_TPB  256
#define HRB     2320                 // bf16 row stride in BYTES (==16 mod 128)
#define SC_WOFF 0                    // W: 48 * 2320 = 111360 B
#define SC_HOFF (48 * HRB)           // h: 16 * 2320 = 37120 B
#define SC_POFF (SC_HOFF + 16 * HRB) // partials: 2 * 6912 floats = 55296 B
#define SC_COFF (SC_POFF + 2 * 6912 * 4)
#define SC_SMEM (SC_COFF + 192 * 4)  // total 204,544 + 768 B

__device__ __forceinline__ float sigm_(float x) { return 1.f / (1.f + __expf(-x)); }
__device__ __forceinline__ float tanh_(float x) {
    float t = __expf(-2.f * fabsf(x));
    float r = (1.f - t) / (1.f + t);
    return x < 0.f ? -r : r;
}
__device__ __forceinline__ void red_release_add(unsigned* p) {
    asm volatile("red.release.gpu.global.add.u32 [%0], %1;" :: "l"(p), "r"(1u) : "memory");
}
__device__ __forceinline__ unsigned ld_relaxed(const unsigned* p) {
    unsigned v;
    asm volatile("ld.relaxed.gpu.global.u32 %0, [%1];" : "=r"(v) : "l"(p) : "memory");
    return v;
}
__device__ __forceinline__ unsigned bfhi2_(float a, float b) {
    __nv_bfloat162 t(__float2bfloat16(a), __float2bfloat16(b));
    return *(unsigned*)&t;
}
__device__ __forceinline__ unsigned bflo2_(float a, float b) {
    float ha = __bfloat162float(__float2bfloat16(a));
    float hb = __bfloat162float(__float2bfloat16(b));
    __nv_bfloat162 t(__float2bfloat16(a - ha), __float2bfloat16(b - hb));
    return *(unsigned*)&t;
}

__global__ void flags_zero_kernel()
{
    g_cnt[threadIdx.x * 8] = 0u;
}

__global__ __launch_bounds__(SC_TPB, 1) void lstm_scan_kernel(
    const float* __restrict__ xpAll,   // [M][3072], dir offset 1536
    const float* __restrict__ WhhF, const float* __restrict__ WhhB,
    float* __restrict__ out)
{
    extern __shared__ char smraw[];
    uint32_t sbw = smem_u32_(smraw);           // W bf16 [48 rows][1152 logical]
    uint32_t sbh = sbw + SC_HOFF;              // h bf16 [16 rows][1152 logical]
    float* s_p = (float*)(smraw + SC_POFF);    // [2][16*48*9]
    float* s_c = (float*)(smraw + SC_COFF);    // [192]

    int tid  = threadIdx.x;
    int wrp  = tid >> 5;
    int lane = tid & 31;
    int dir = blockIdx.x >> 5;
    int ug  = blockIdx.x & 31;
    int u0  = ug * 12;
    const float* Whh = dir ? WhhB : WhhF;

    // preload Whh as logical-split bf16: region 0=hi, 1=lo, 2=hi ([hi|lo|hi])
    for (int idx = tid; idx < 48 * 288; idx += SC_TPB) {
        int r  = idx / 288;
        int c4 = (idx % 288) * 4;          // logical col (0..1148)
        int reg = c4 / 384, src = c4 % 384;
        int grow = (r / 12) * H_ + u0 + (r % 12);
        float4 v = __ldg((const float4*)(Whh + (size_t)grow * H_ + src));
        uint2 pk;
        if (reg != 1) { pk.x = bfhi2_(v.x, v.y); pk.y = bfhi2_(v.z, v.w); }
        else         { pk.x = bflo2_(v.x, v.y); pk.y = bflo2_(v.z, v.w); }
        *(uint2*)(smraw + (size_t)r * HRB + (size_t)c4 * 2) = pk;
    }
    // zero h region (all 1152 logical cols, 16 rows)
    for (int idx = tid; idx < 16 * 288; idx += SC_TPB) {
        int r = idx / 288, c4 = (idx % 288) * 4;
        *(uint2*)(smraw + SC_HOFF + (size_t)r * HRB + (size_t)c4 * 2) = make_uint2(0u, 0u);
    }
    if (tid < 192) s_c[tid] = 0.f;
    __syncthreads();

    int kw = 144 * wrp;                       // this warp's logical k base
    // ldmatrix lane bases (strides conflict-free: 2320 % 128 == 16)
    uint32_t aoff = (uint32_t)(lane & 15) * HRB + (uint32_t)(lane >> 4) * 16
                  + (uint32_t)kw * 2;
    uint32_t boff = (uint32_t)((lane & 7) + ((lane >> 4) << 3)) * HRB
                  + (uint32_t)((lane >> 3) & 1) * 16 + (uint32_t)kw * 2;

    int cb = tid / 12, cu = tid % 12;         // combine role (tid < 192)
    unsigned* mycnt = &g_cnt[(dir * 32 + ug) * 8];
    int buf = 0;

    for (int step = 0; step < S_; step++) {
        int tt = dir ? (S_ - 1 - step) : step;

        // prefetch xproj (combine threads)
        float xpre[4] = {0.f, 0.f, 0.f, 0.f};
        if (tid < 192) {
            size_t base = ((size_t)(cb * S_ + tt)) * G8 + (size_t)dir * G4 + u0 + cu;
#pragma unroll
            for (int g = 0; g < 4; g++) xpre[g] = __ldg(xpAll + base + g * H_);
        }

        if (step > 0) {
            // poll this warp's 12 producers (units (12*wrp + l) mod 32)
            unsigned target = 192u * (unsigned)step;
            if (lane < 12) {
                const unsigned* f = &g_cnt[(dir * 32 + ((12 * wrp + lane) & 31)) * 8];
                while (ld_relaxed(f) < target) { }
            }
            __syncwarp();
            asm volatile("fence.acq_rel.gpu;" ::: "memory");
            int tp = dir ? (tt + 1) : (tt - 1);
            // stage+convert this warp's 144 logical cols x 16 rows
#pragma unroll
            for (int e = 0; e < 18; e++) {
                int flat = lane + 32 * e;          // 0..575
                int row  = flat / 36;
                int c4   = (flat % 36) * 4;
                int k    = kw + c4;
                int reg  = k / 384, src = k % 384;
                float4 v = __ldcg((const float4*)(out +
                    ((size_t)(row * S_ + tp)) * 768 + dir * H_ + src));
                uint2 pk;
                if (reg < 2) { pk.x = bfhi2_(v.x, v.y); pk.y = bfhi2_(v.z, v.w); }
                else         { pk.x = bflo2_(v.x, v.y); pk.y = bflo2_(v.z, v.w); }
                *(uint2*)(smraw + SC_HOFF + (size_t)row * HRB + (size_t)k * 2) = pk;
            }
            __syncwarp();
        }

        // mma: acc[6 ntiles][4], 9 ksteps x (1 A-ldsm + 3 B-ldsm + 6 mma)
        float acc[6][4];
#pragma unroll
        for (int nt = 0; nt < 6; nt++)
#pragma unroll
            for (int e = 0; e < 4; e++) acc[nt][e] = 0.f;

#pragma unroll
        for (int s = 0; s < 9; s++) {
            uint32_t ko = (uint32_t)s * 32;
            uint32_t a[4], b[3][4];
            LDSM4_(a[0], a[1], a[2], a[3], sbh + aoff + ko);
#pragma unroll
            for (int g2 = 0; g2 < 3; g2++)
                LDSM4_(b[g2][0], b[g2][1], b[g2][2], b[g2][3],
                       sbw + boff + (uint32_t)g2 * (16 * HRB) + ko);
#pragma unroll
            for (int nt = 0; nt < 6; nt++) {
                int g2 = nt >> 1, h = (nt & 1) * 2;
                MMA16816_(acc[nt], a, b[g2][h], b[g2][h + 1]);
            }
        }

        // partial store: D rows = batches, cols = gate-rows; s_p[(b*48+r)*9 + w]
        {
            float* pb = s_p + buf * 6912;
            int bl = lane >> 2;
#pragma unroll
            for (int nt = 0; nt < 6; nt++) {
                int c = nt * 8 + 2 * (lane & 3);
                pb[(bl * 48 + c) * 9 + wrp]           = acc[nt][0];
                pb[(bl * 48 + c + 1) * 9 + wrp]       = acc[nt][1];
                pb[((bl + 8) * 48 + c) * 9 + wrp]     = acc[nt][2];
                pb[((bl + 8) * 48 + c + 1) * 9 + wrp] = acc[nt][3];
            }
        }
        __syncthreads();

        // combine: tid<192 -> one per (batch, unit)
        if (tid < 192) {
            const float* pbase = s_p + buf * 6912 + cb * 48 * 9;
            float gate[4];
#pragma unroll
            for (int g = 0; g < 4; g++) {
                const float* pp = pbase + (g * 12 + cu) * 9;
                float s = xpre[g];
#pragma unroll
                for (int w = 0; w < 8; w++) s += pp[w];
                gate[g] = s;
            }
            float c = sigm_(gate[1]) * s_c[tid] + sigm_(gate[0]) * tanh_(gate[2]);
            s_c[tid] = c;
            float h = sigm_(gate[3]) * tanh_(c);
            __stcg(out + ((size_t)(cb * S_ + tt)) * 768 + dir * H_ + u0 + cu, h);
            red_release_add(mycnt);
        }
        buf ^= 1;
    }
}

// ---------------- windowed attention ----------------
__global__ __launch_bounds__(256) void attn_kernel(
    float* __restrict__ hcat, const float* __restrict__ attnW,
    const int* __restrict__ wsp)
{
    int gw   = (int)((blockIdx.x * blockDim.x + threadIdx.x) >> 5);
    int lane = threadIdx.x & 31;
    if (gw >= M_) return;
    int b = gw >> 10, i = gw & 1023;
    int Wn = wsp ? *wsp : 32;
    if (Wn < 0) Wn = 0;
    if (Wn > S_) Wn = S_;

    const float* w2 = attnW + H_;
    const float* w3 = attnW + 2 * H_;
    const float* hi = hcat + (size_t)gw * 768;

    float v[12], a[12];
#pragma unroll
    for (int q = 0; q < 12; q++) {
        int k = q * 32 + lane;
        v[q] = w2[k] + hi[k] * w3[k];
        a[q] = 0.f;
    }
    float m = -1e30f, Z = 0.f;
    int jlo = i - Wn; if (jlo < 0) jlo = 0;
    int jhi = i + Wn; if (jhi > S_ - 1) jhi = S_ - 1;

    for (int j = jlo; j <= jhi; j++) {
        const float* hj = hcat + ((size_t)(b * S_ + j)) * 768;
        float hq[12];
        float s = 0.f;
#pragma unroll
        for (int q = 0; q < 12; q++) {
            hq[q] = hj[q * 32 + lane];
            s = fmaf(v[q], hq[q], s);
        }
#pragma unroll
        for (int o = 16; o; o >>= 1) s += __shfl_xor_sync(0xffffffffu, s, o);
        float mn = fmaxf(m, s);
        float r  = __expf(m - mn);
        float e  = __expf(s - mn);
        Z = Z * r + e;
#pragma unroll
        for (int q = 0; q < 12; q++) a[q] = a[q] * r + e * hq[q];
        m = mn;
    }
    float inv = 1.f / Z;
#pragma unroll
    for (int q = 0; q < 12; q++)
        hcat[(size_t)gw * 768 + H_ + q * 32 + lane] = a[q] * inv;
}

// ---------------- final gemv ----------------
__global__ __launch_bounds__(256) void gemv_kernel(
    const float* __restrict__ A, const float* __restrict__ w,
    const float* __restrict__ b, float* __restrict__ out)
{
    int gw   = (int)((blockIdx.x * blockDim.x + threadIdx.x) >> 5);
    int lane = threadIdx.x & 31;
    if (gw >= M_) return;
    float s = 0.f;
#pragma unroll
    for (int k = lane; k < 96; k += 32) s = fmaf(A[(size_t)gw * 96 + k], w[k], s);
#pragma unroll
    for (int o = 16; o; o >>= 1) s += __shfl_xor_sync(0xffffffffu, s, o);
    if (lane == 0) out[gw] = s + b[0];
}

// ---------------- host ----------------
static int pick_by_size(const int* sizes, int n, int want, unsigned char* used)
{
    for (int i = 0; i < n; i++) {
        if (!used[i] && sizes[i] == want) { used[i] = 1; return i; }
    }
    return -1;
}

extern "C" void kernel_launch(void* const* d_in, const int* in_sizes, int n_in,
                              void* d_out, int out_size)
{
    unsigned char used[64];
    for (int i = 0; i < 64; i++) used[i] = 0;
    int ix[24];
    ix[0]  = pick_by_size(in_sizes, n_in, 12582912, used);
    ix[1]  = pick_by_size(in_sizes, n_in, 1179648,  used);
    ix[2]  = pick_by_size(in_sizes, n_in, 589824,   used);
    ix[3]  = pick_by_size(in_sizes, n_in, 1536,     used);
    ix[4]  = pick_by_size(in_sizes, n_in, 1179648,  used);
    ix[5]  = pick_by_size(in_sizes, n_in, 589824,   used);
    ix[6]  = pick_by_size(in_sizes, n_in, 1536,     used);
    ix[7]  = pick_by_size(in_sizes, n_in, 294912,   used);
    ix[8]  = pick_by_size(in_sizes, n_in, 384,      used);
    ix[9]  = pick_by_size(in_sizes, n_in, 1152,     used);
    ix[10] = pick_by_size(in_sizes, n_in, 1,        used);
    ix[11] = pick_by_size(in_sizes, n_in, 1179648,  used);
    ix[12] = pick_by_size(in_sizes, n_in, 589824,   used);
    ix[13] = pick_by_size(in_sizes, n_in, 1536,     used);
    ix[14] = pick_by_size(in_sizes, n_in, 1179648,  used);
    ix[15] = pick_by_size(in_sizes, n_in, 589824,   used);
    ix[16] = pick_by_size(in_sizes, n_in, 1536,     used);
    ix[17] = pick_by_size(in_sizes, n_in, 98304,    used);
    ix[18] = pick_by_size(in_sizes, n_in, 256,      used);
    ix[19] = pick_by_size(in_sizes, n_in, 24576,    used);
    ix[20] = pick_by_size(in_sizes, n_in, 96,       used);
    ix[21] = pick_by_size(in_sizes, n_in, 96,       used);
    ix[22] = pick_by_size(in_sizes, n_in, 1,        used);
    ix[23] = pick_by_size(in_sizes, n_in, 1,        used);

    bool ok = true;
    for (int i = 0; i < 23; i++) if (ix[i] < 0) ok = false;
    if (!ok) {
        for (int i = 0; i < 24; i++) ix[i] = (i < n_in) ? i : -1;
    }

    const float* x      = (const float*)d_in[ix[0]];
    const float* l1Wihf = (const float*)d_in[ix[1]];
    const float* l1Whhf = (const float*)d_in[ix[2]];
    const float* l1bf   = (const float*)d_in[ix[3]];
    const float* l1Wihb = (const float*)d_in[ix[4]];
    const float* l1Whhb = (const float*)d_in[ix[5]];
    const float* l1bb   = (const float*)d_in[ix[6]];
    const float* fc1W   = (const float*)d_in[ix[7]];
    const float* fc1b   = (const float*)d_in[ix[8]];
    const float* attnW  = (const float*)d_in[ix[9]];
    const float* l2Wihf = (const float*)d_in[ix[11]];
    const float* l2Whhf = (const float*)d_in[ix[12]];
    const float* l2bf   = (const float*)d_in[ix[13]];
    const float* l2Wihb = (const float*)d_in[ix[14]];
    const float* l2Whhb = (const float*)d_in[ix[15]];
    const float* l2bb   = (const float*)d_in[ix[16]];
    const float* W1     = (const float*)d_in[ix[17]];
    const float* b1     = (const float*)d_in[ix[18]];
    const float* W2     = (const float*)d_in[ix[19]];
    const float* b2     = (const float*)d_in[ix[20]];
    const float* W3     = (const float*)d_in[ix[21]];
    const float* b3     = (const float*)d_in[ix[22]];
    const int*   wsp    = (ix[23] >= 0) ? (const int*)d_in[ix[23]] : nullptr;

    float *xpAll, *lstm, *hcat, *h2, *mlp1, *mlp2;
    __nv_bfloat16 *A2, *W2b, *Wfc;
    cudaGetSymbolAddress((void**)&xpAll, g_xpAll);
    cudaGetSymbolAddress((void**)&lstm,  g_lstm);
    cudaGetSymbolAddress((void**)&hcat,  g_hcat);
    cudaGetSymbolAddress((void**)&h2,    g_h2);
    cudaGetSymbolAddress((void**)&mlp1,  g_mlp1);
    cudaGetSymbolAddress((void**)&mlp2,  g_mlp2);
    cudaGetSymbolAddress((void**)&A2,    g_A2);
    cudaGetSymbolAddress((void**)&W2b,   g_W2);
    cudaGetSymbolAddress((void**)&Wfc,   g_Wfc);

    cudaFuncSetAttribute(lstm_scan_kernel,
                         cudaFuncAttributeMaxDynamicSharedMemorySize, SC_SMEM);
    size_t tgsm = 65536;
    cudaFuncSetAttribute(tgemm_kernel,
                         cudaFuncAttributeMaxDynamicSharedMemorySize, (int)tgsm);

    const int APQ   = M_ * 192;
    const int WPQ   = G4 * 192;
    const int FC1PQ = H_ * 192;
    dim3 xp_grid(G8 / 128, M_ / 128);
    dim3 fc_grid(H_ / 128, M_ / 128);

    // fc1W prepped ONCE
    split_prep_kernel<<<(FC1PQ + 255) / 256, 256>>>(fc1W, Wfc, FC1PQ, 1);

    // ---- layer 1 ----
    split_prep_kernel<<<(APQ + 255) / 256, 256>>>(x, A2, APQ, 0);
    split_prep_kernel<<<(WPQ + 255) / 256, 256>>>(l1Wihf, W2b, WPQ, 1);
    split_prep_kernel<<<(WPQ + 255) / 256, 256>>>(l1Wihb, W2b + (size_t)G4 * K2, WPQ, 1);
    tgemm_kernel<<<xp_grid, 256, tgsm>>>(A2, W2b, l1bf, l1bb, 12, xpAll, G8);
    flags_zero_kernel<<<1, 128>>>();
    lstm_scan_kernel<<<SC_NCTA, SC_TPB, SC_SMEM>>>(xpAll, l1Whhf, l1Whhb, lstm);

    // fc1 (tensor) -> h
    split_prep_kernel<<<(APQ + 255) / 256, 256>>>(lstm, A2, APQ, 0);
    tgemm_kernel<<<fc_grid, 256, tgsm>>>(A2, Wfc, fc1b, fc1b, 3, hcat, 768);

    // windowed attention
    attn_kernel<<<M_ / 8, 256>>>(hcat, attnW, wsp);

    // ---- layer 2 ----
    split_prep_kernel<<<(APQ + 255) / 256, 256>>>(hcat, A2, APQ, 0);
    split_prep_kernel<<<(WPQ + 255) / 256, 256>>>(l2Wihf, W2b, WPQ, 1);
    split_prep_kernel<<<(WPQ + 255) / 256, 256>>>(l2Wihb, W2b + (size_t)G4 * K2, WPQ, 1);
    tgemm_kernel<<<xp_grid, 256, tgsm>>>(A2, W2b, l2bf, l2bb, 12, xpAll, G8);
    flags_zero_kernel<<<1, 128>>>();
    lstm_scan_kernel<<<SC_NCTA, SC_TPB, SC_SMEM>>>(xpAll, l2Whhf, l2Whhb, lstm);

    // fc1 again (tensor) -> h2
    split_prep_kernel<<<(APQ + 255) / 256, 256>>>(lstm, A2, APQ, 0);
    tgemm_kernel<<<fc_grid, 256, tgsm>>>(A2, Wfc, fc1b, fc1b, 3, h2, H_);

    // MLP head
    gemm_bias_kernel<1><<<dim3(2, M_ / 128), 256>>>(h2,   W1, b1, mlp1, M_, 256, H_,  256);
    gemm_bias_kernel<1><<<dim3(1, M_ / 128), 256>>>(mlp1, W2, b2, mlp2, M_, 96,  256, 96);
    gemv_kernel<<<M_ / 8, 256>>>(mlp2, W3, b3, (float*)d_out);
}

// round 16
// speedup vs baseline: 2.3187x; 2.3187x over previous
#include <cuda_runtime.h>
#include <cuda_bf16.h>
#include <cstdint>
#include <cstddef>

// Problem dims
#define B_   16
#define H_   384
#define G4   1536          // 4*H
#define G8   3072          // both dirs
#define M_   16384         // B*S
#define S_   1024
#define K2   2304          // split-GEMM K'' = 3*768

// ---------------- scratch ----------------
__device__ __align__(256) float g_xpAll [(size_t)M_ * G8];
__device__ __align__(256) float g_lstm  [(size_t)M_ * 768];
__device__ __align__(256) float g_hcat  [(size_t)M_ * 768];
__device__ __align__(256) float g_h2    [(size_t)M_ * H_];
__device__ __align__(256) float g_mlp1  [(size_t)M_ * 256];
__device__ __align__(256) float g_mlp2  [(size_t)M_ * 96];
__device__ __align__(256) __nv_bfloat16 g_W2 [(size_t)G8 * K2];
__device__ __align__(256) __nv_bfloat16 g_Wfc[(size_t)H_ * K2];
__device__ __align__(256) unsigned g_cnt[128 * 8];

// ---------------- packed f32x2 helpers ----------------
__device__ __forceinline__ void fma2_(unsigned long long& d,
                                      unsigned long long a,
                                      unsigned long long b) {
    asm("fma.rn.f32x2 %0, %1, %2, %0;" : "+l"(d) : "l"(a), "l"(b));
}
__device__ __forceinline__ unsigned long long pack2_(float x, float y) {
    unsigned long long d;
    asm("mov.b64 %0, {%1, %2};" : "=l"(d) : "f"(x), "f"(y));
    return d;
}
__device__ __forceinline__ float2 unpack2_(unsigned long long v) {
    float2 r;
    asm("mov.b64 {%0, %1}, %2;" : "=f"(r.x), "=f"(r.y) : "l"(v));
    return r;
}

// ---------------- generic SIMT GEMM (MLP head) ----------------
template<int ACT>
__global__ __launch_bounds__(256, 2) void gemm_bias_kernel(
    const float* __restrict__ A, const float* __restrict__ W,
    const float* __restrict__ bias, float* __restrict__ C,
    int M, int N, int K, int ldc)
{
    __shared__ float sA[16][132];
    __shared__ float sB[16][132];
    int tid = threadIdx.x;
    int m0 = blockIdx.y * 128;
    int n0 = blockIdx.x * 128;
    int tx = tid & 15, ty = tid >> 4;

    unsigned long long acc2[8][4];
#pragma unroll
    for (int i = 0; i < 8; i++)
#pragma unroll
        for (int j = 0; j < 4; j++) acc2[i][j] = 0ULL;

    for (int k0 = 0; k0 < K; k0 += 16) {
#pragma unroll
        for (int e = 0; e < 2; e++) {
            int f4 = tid + 256 * e;
            int r  = f4 >> 2;
            int c4 = (f4 & 3) << 2;
            float4 av = *(const float4*)(A + (size_t)(m0 + r) * K + k0 + c4);
            sA[c4 + 0][r] = av.x; sA[c4 + 1][r] = av.y;
            sA[c4 + 2][r] = av.z; sA[c4 + 3][r] = av.w;
            int n = n0 + r;
            float4 wv = make_float4(0.f, 0.f, 0.f, 0.f);
            if (n < N) wv = *(const float4*)(W + (size_t)n * K + k0 + c4);
            sB[c4 + 0][r] = wv.x; sB[c4 + 1][r] = wv.y;
            sB[c4 + 2][r] = wv.z; sB[c4 + 3][r] = wv.w;
        }
        __syncthreads();
#pragma unroll
        for (int kk = 0; kk < 16; kk++) {
            float a[8];
            *(float4*)&a[0] = *(const float4*)&sA[kk][ty * 8];
            *(float4*)&a[4] = *(const float4*)&sA[kk][ty * 8 + 4];
            ulonglong2 bv0 = *(const ulonglong2*)&sB[kk][tx * 8];
            ulonglong2 bv1 = *(const ulonglong2*)&sB[kk][tx * 8 + 4];
            unsigned long long b2[4] = {bv0.x, bv0.y, bv1.x, bv1.y};
#pragma unroll
            for (int i = 0; i < 8; i++) {
                unsigned long long a2 = pack2_(a[i], a[i]);
#pragma unroll
                for (int j = 0; j < 4; j++)
                    fma2_(acc2[i][j], a2, b2[j]);
            }
        }
        __syncthreads();
    }

#pragma unroll
    for (int i = 0; i < 8; i++) {
        int m = m0 + ty * 8 + i;
#pragma unroll
        for (int j2 = 0; j2 < 4; j2++) {
            float2 p = unpack2_(acc2[i][j2]);
            int n = n0 + tx * 8 + j2 * 2;
            if (n < N) {
                float v0 = p.x + bias[n];
                if (ACT) v0 = fmaxf(v0, 0.f);
                C[(size_t)m * ldc + n] = v0;
            }
            if (n + 1 < N) {
                float v1 = p.y + bias[n + 1];
                if (ACT) v1 = fmaxf(v1, 0.f);
                C[(size_t)m * ldc + n + 1] = v1;
            }
        }
    }
}

// ---------------- bf16 split prep (weights only now) ----------------
// mode 1 (W): [hi | lo | hi]
__global__ __launch_bounds__(256) void split_prep_kernel(
    const float* __restrict__ in, __nv_bfloat16* __restrict__ out,
    int nquads, int mode)
{
    int g = blockIdx.x * blockDim.x + threadIdx.x;
    if (g >= nquads) return;
    int m = g / 192;
    int q = (g % 192) * 4;
    float4 v = *(const float4*)(in + (size_t)m * 768 + q);
    float a[4] = {v.x, v.y, v.z, v.w};
    float h0 = __bfloat162float(__float2bfloat16(a[0]));
    float h1 = __bfloat162float(__float2bfloat16(a[1]));
    float h2 = __bfloat162float(__float2bfloat16(a[2]));
    float h3 = __bfloat162float(__float2bfloat16(a[3]));
    __nv_bfloat162 hi01 = __nv_bfloat162(__float2bfloat16(a[0]), __float2bfloat16(a[1]));
    __nv_bfloat162 hi23 = __nv_bfloat162(__float2bfloat16(a[2]), __float2bfloat16(a[3]));
    __nv_bfloat162 lo01 = __nv_bfloat162(__float2bfloat16(a[0] - h0), __float2bfloat16(a[1] - h1));
    __nv_bfloat162 lo23 = __nv_bfloat162(__float2bfloat16(a[2] - h2), __float2bfloat16(a[3] - h3));
    __nv_bfloat16* o = out + (size_t)m * K2 + q;
    *(__nv_bfloat162*)(o + 0) = hi01;  *(__nv_bfloat162*)(o + 2) = hi23;
    if (mode == 0) {
        *(__nv_bfloat162*)(o + 768)  = hi01;  *(__nv_bfloat162*)(o + 770)  = hi23;
        *(__nv_bfloat162*)(o + 1536) = lo01;  *(__nv_bfloat162*)(o + 1538) = lo23;
    } else {
        *(__nv_bfloat162*)(o + 768)  = lo01;  *(__nv_bfloat162*)(o + 770)  = lo23;
        *(__nv_bfloat162*)(o + 1536) = hi01;  *(__nv_bfloat162*)(o + 1538) = hi23;
    }
}

// ---------------- warp-MMA bf16 GEMM with fused A conversion ----------------
// A is fp32 [M][768]; logical A'' = [hi | hi | lo] (K2=2304) converted in-register.
#define TG_NBLK 36

__device__ __forceinline__ uint32_t smem_u32_(const void* p) {
    uint32_t a;
    asm("{ .reg .u64 t; cvta.to.shared.u64 t, %1; cvt.u32.u64 %0, t; }" : "=r"(a) : "l"(p));
    return a;
}
__device__ __forceinline__ uint32_t swz_(uint32_t off) {
    return off ^ ((off >> 3) & 0x70);
}
__device__ __forceinline__ void cp16_(uint32_t s, const void* g) {
    asm volatile("cp.async.cg.shared.global [%0], [%1], 16;" :: "r"(s), "l"(g) : "memory");
}
__device__ __forceinline__ void sts4u_(uint32_t addr, uint32_t a, uint32_t b,
                                       uint32_t c, uint32_t d) {
    asm volatile("st.shared.v4.b32 [%0], {%1, %2, %3, %4};"
                 :: "r"(addr), "r"(a), "r"(b), "r"(c), "r"(d) : "memory");
}
__device__ __forceinline__ unsigned bfhi2_(float a, float b) {
    __nv_bfloat162 t(__float2bfloat16(a), __float2bfloat16(b));
    return *(unsigned*)&t;
}
__device__ __forceinline__ unsigned bflo2_(float a, float b) {
    float ha = __bfloat162float(__float2bfloat16(a));
    float hb = __bfloat162float(__float2bfloat16(b));
    __nv_bfloat162 t(__float2bfloat16(a - ha), __float2bfloat16(b - hb));
    return *(unsigned*)&t;
}
#define LDSM4_(d0, d1, d2, d3, addr) \
    asm volatile("ldmatrix.sync.aligned.m8n8.x4.shared.b16 {%0,%1,%2,%3}, [%4];" \
                 : "=r"(d0), "=r"(d1), "=r"(d2), "=r"(d3) : "r"(addr))
#define MMA16816_(c, a, b0, b1) \
    asm volatile("mma.sync.aligned.m16n8k16.row.col.f32.bf16.bf16.f32 " \
                 "{%0,%1,%2,%3}, {%4,%5,%6,%7}, {%8,%9}, {%0,%1,%2,%3};" \
                 : "+f"((c)[0]), "+f"((c)[1]), "+f"((c)[2]), "+f"((c)[3]) \
                 : "r"((a)[0]), "r"((a)[1]), "r"((a)[2]), "r"((a)[3]), \
                   "r"(b0), "r"(b1))

__global__ __launch_bounds__(256) void tgemm_kernel(
    const float* __restrict__ Afp,
    const __nv_bfloat16* __restrict__ W2,
    const float* __restrict__ biasA,
    const float* __restrict__ biasB,
    int nsplit,
    float* __restrict__ C, int ldc)
{
    extern __shared__ char smraw[];
    uint32_t sb = smem_u32_(smraw);
    int tid  = threadIdx.x;
    int wid  = tid >> 5;
    int lane = tid & 31;
    int n0 = blockIdx.x * 128;
    int m0 = blockIdx.y * 128;
    int wm = (wid & 3) * 32;
    int wn = (wid >> 2) * 64;

    const float* bp = ((int)blockIdx.x < nsplit) ? biasA : biasB;
    int coff = ((int)blockIdx.x < nsplit) ? 0 : nsplit * 128;

    float acc[2][8][4];
#pragma unroll
    for (int mt = 0; mt < 2; mt++)
#pragma unroll
        for (int nt = 0; nt < 8; nt++)
#pragma unroll
            for (int e = 0; e < 4; e++) acc[mt][nt][e] = 0.f;

    int arow = wm + (lane & 15);
    uint32_t arowoff = (uint32_t)arow * 128;
    uint32_t amask   = (uint32_t)(arow & 7) << 4;
    uint32_t akh     = (uint32_t)(lane >> 4) * 16;

    int brow = wn + (lane & 7) + ((lane >> 4) << 3);
    uint32_t browoff = (uint32_t)brow * 128;
    uint32_t bmask   = (uint32_t)(brow & 7) << 4;
    uint32_t bkh     = (uint32_t)((lane >> 3) & 1) * 16;

    // per-thread chunk roles (fixed across blocks)
    int rowi[4], chi[4];
    uint32_t soi[4];
#pragma unroll
    for (int i = 0; i < 4; i++) {
        int cid = tid + 256 * i;
        rowi[i] = cid >> 3;
        chi[i]  = cid & 7;
        soi[i]  = swz_((uint32_t)rowi[i] * 128 + (uint32_t)chi[i] * 16);
    }

    float4 av[4][2];

    // prologue: A fp32 loads (blk 0, region hi, src 0) + W cp.async blk 0
#pragma unroll
    for (int i = 0; i < 4; i++) {
        const float* base = Afp + (size_t)(m0 + rowi[i]) * 768 + chi[i] * 8;
        av[i][0] = __ldg((const float4*)base);
        av[i][1] = __ldg((const float4*)(base + 4));
        cp16_(sb + 32768 + soi[i], W2 + (size_t)(n0 + rowi[i]) * K2 + chi[i] * 8);
    }
    asm volatile("cp.async.commit_group;" ::: "memory");
#pragma unroll
    for (int i = 0; i < 4; i++) {
        sts4u_(sb + soi[i],
               bfhi2_(av[i][0].x, av[i][0].y), bfhi2_(av[i][0].z, av[i][0].w),
               bfhi2_(av[i][1].x, av[i][1].y), bfhi2_(av[i][1].z, av[i][1].w));
    }

    for (int blk = 0; blk < TG_NBLK; blk++) {
        int bufc = blk & 1;
        int bufn = (blk + 1) & 1;
        bool more = (blk + 1 < TG_NBLK);
        if (more) {
            int regn = (blk + 1) / 12;
            int sc   = ((blk + 1) % 12) * 64;
            size_t gk = (size_t)(blk + 1) * 64;
#pragma unroll
            for (int i = 0; i < 4; i++) {
                const float* base = Afp + (size_t)(m0 + rowi[i]) * 768 + sc + chi[i] * 8;
                av[i][0] = __ldg((const float4*)base);
                av[i][1] = __ldg((const float4*)(base + 4));
                cp16_(sb + 32768 + bufn * 16384 + soi[i],
                      W2 + (size_t)(n0 + rowi[i]) * K2 + gk + chi[i] * 8);
            }
            asm volatile("cp.async.commit_group;" ::: "memory");
            asm volatile("cp.async.wait_group 1;" ::: "memory");
            (void)regn;
        } else {
            asm volatile("cp.async.wait_group 0;" ::: "memory");
        }
        __syncthreads();

        uint32_t abuf = sb + bufc * 16384;
        uint32_t bbuf = sb + 32768 + bufc * 16384;
#pragma unroll
        for (int kk = 0; kk < 4; kk++) {
            uint32_t acol = (akh + (uint32_t)kk * 32) ^ amask;
            uint32_t bcol = (bkh + (uint32_t)kk * 32) ^ bmask;
            uint32_t a[2][4], b[4][4];
#pragma unroll
            for (int mt = 0; mt < 2; mt++)
                LDSM4_(a[mt][0], a[mt][1], a[mt][2], a[mt][3],
                       abuf + arowoff + mt * 2048 + acol);
#pragma unroll
            for (int g = 0; g < 4; g++)
                LDSM4_(b[g][0], b[g][1], b[g][2], b[g][3],
                       bbuf + browoff + g * 2048 + bcol);
#pragma unroll
            for (int mt = 0; mt < 2; mt++)
#pragma unroll
                for (int nt = 0; nt < 8; nt++) {
                    int g = nt >> 1, h = (nt & 1) * 2;
                    MMA16816_(acc[mt][nt], a[mt], b[g][h], b[g][h + 1]);
                }
        }
        // convert + store A for blk+1 (loads had the whole compute to land)
        if (more) {
            bool hi = ((blk + 1) / 12) < 2;
            uint32_t adst = sb + bufn * 16384;
            if (hi) {
#pragma unroll
                for (int i = 0; i < 4; i++)
                    sts4u_(adst + soi[i],
                           bfhi2_(av[i][0].x, av[i][0].y), bfhi2_(av[i][0].z, av[i][0].w),
                           bfhi2_(av[i][1].x, av[i][1].y), bfhi2_(av[i][1].z, av[i][1].w));
            } else {
#pragma unroll
                for (int i = 0; i < 4; i++)
                    sts4u_(adst + soi[i],
                           bflo2_(av[i][0].x, av[i][0].y), bflo2_(av[i][0].z, av[i][0].w),
                           bflo2_(av[i][1].x, av[i][1].y), bflo2_(av[i][1].z, av[i][1].w));
            }
        }
        __syncthreads();
    }

#pragma unroll
    for (int mt = 0; mt < 2; mt++)
#pragma unroll
        for (int nt = 0; nt < 8; nt++) {
            int row = m0 + wm + mt * 16 + (lane >> 2);
            int col = n0 + wn + nt * 8 + (lane & 3) * 2;
            float2 bv = *(const float2*)(bp + (col - coff));
            float2 o0 = make_float2(acc[mt][nt][0] + bv.x, acc[mt][nt][1] + bv.y);
            float2 o1 = make_float2(acc[mt][nt][2] + bv.x, acc[mt][nt][3] + bv.y);
            *(float2*)(C + (size_t)row * ldc + col) = o0;
            *(float2*)(C + (size_t)(row + 8) * ldc + col) = o1;
        }
}

// ---------------- LSTM recurrent scan (R14/R12: warp-autonomous, Whh in regs) ----------------
#define NUX   12
#define NBX   8
#define HSTR  392
#define PBUF  (NBX * 48 * 32)
#define NCTA  128
#define TPB   256

__device__ __forceinline__ float sigm_(float x) { return 1.f / (1.f + __expf(-x)); }
__device__ __forceinline__ float tanh_(float x) {
    float t = __expf(-2.f * fabsf(x));
    float r = (1.f - t) / (1.f + t);
    return x < 0.f ? -r : r;
}
__device__ __forceinline__ void red_release_add(unsigned* p) {
    asm volatile("red.release.gpu.global.add.u32 [%0], %1;" :: "l"(p), "r"(1u) : "memory");
}
__device__ __forceinline__ unsigned ld_relaxed(const unsigned* p) {
    unsigned v;
    asm volatile("ld.relaxed.gpu.global.u32 %0, [%1];" : "=r"(v) : "l"(p) : "memory");
    return v;
}

__global__ void flags_zero_kernel()
{
    g_cnt[threadIdx.x * 8] = 0u;
}

__global__ __launch_bounds__(TPB, 1) void lstm_scan_kernel(
    const float* __restrict__ xpAll,   // [M][3072], dir offset 1536
    const float* __restrict__ WhhF, const float* __restrict__ WhhB,
    float* __restrict__ out)
{
    extern __shared__ float sm[];
    float* s_h = sm;
    float* s_p = s_h + NBX * HSTR;
    float* s_c = s_p + 2 * PBUF;

    int tid  = threadIdx.x;
    int wrp  = tid >> 5;
    int lane = tid & 31;
    int dir = blockIdx.x >> 6;
    int bg  = (blockIdx.x >> 5) & 1;
    int ug  = blockIdx.x & 31;
    int u0  = ug * NUX;
    int bb0 = bg * NBX;
    int clique = dir * 2 + bg;
    const float* Whh = dir ? WhhB : WhhF;

    int ql    = lane & 3;
    int rt    = lane >> 2;
    int kbase = wrp * 48 + ql * 12;
    int r0    = rt * 6;
    int qg    = wrp * 4 + ql;

    unsigned long long w2[3][12];
#pragma unroll
    for (int rp = 0; rp < 3; rp++) {
        int ra = r0 + 2 * rp, rb = ra + 1;
        const float* Wa = Whh + (size_t)((ra / NUX) * H_ + u0 + (ra % NUX)) * H_ + kbase;
        const float* Wb = Whh + (size_t)((rb / NUX) * H_ + u0 + (rb % NUX)) * H_ + kbase;
#pragma unroll
        for (int k = 0; k < 12; k++)
            w2[rp][k] = pack2_(__ldg(Wa + k), __ldg(Wb + k));
    }
    if (tid < NBX * NUX) s_c[tid] = 0.f;

    {
        int kw = wrp * 48;
#pragma unroll
        for (int e = 0; e < 3; e++) {
            int idx = lane + 32 * e;
            int b   = idx / 12;
            int c4  = (idx % 12) * 4;
            *(float4*)&s_h[b * HSTR + kw + c4] = make_float4(0.f, 0.f, 0.f, 0.f);
        }
    }
    __syncthreads();

    unsigned* mycnt = &g_cnt[(clique * 32 + ug) * 8];
    int cb = tid / NUX, cu = tid % NUX;
    int buf = 0;

    for (int step = 0; step < S_; step++) {
        int tt = dir ? (S_ - 1 - step) : step;

        float xpre[4] = {0.f, 0.f, 0.f, 0.f};
        if (tid < NBX * NUX) {
            size_t base = ((size_t)((bb0 + cb) * S_ + tt)) * G8 + (size_t)dir * G4 + u0 + cu;
#pragma unroll
            for (int g = 0; g < 4; g++) xpre[g] = __ldg(xpAll + base + g * H_);
        }

        if (step > 0) {
            unsigned target = 96u * (unsigned)step;
            if (lane < 4) {
                const unsigned* f = &g_cnt[(clique * 32 + (wrp << 2) + lane) * 8];
                while (ld_relaxed(f) < target) { }
            }
            __syncwarp();
            asm volatile("fence.acq_rel.gpu;" ::: "memory");
            int tp = dir ? (tt + 1) : (tt - 1);
            int kw = wrp * 48;
#pragma unroll
            for (int e = 0; e < 3; e++) {
                int idx = lane + 32 * e;
                int b   = idx / 12;
                int c4  = (idx % 12) * 4;
                int k   = kw + c4;
                const float4* src = (const float4*)(out +
                    ((size_t)((bb0 + b) * S_ + tp)) * 768 + dir * H_ + k);
                *(float4*)&s_h[b * HSTR + k] = __ldcg(src);
            }
            __syncwarp();
        }

        unsigned long long acc2[NBX][3];
#pragma unroll
        for (int b = 0; b < NBX; b++)
#pragma unroll
            for (int rp = 0; rp < 3; rp++) acc2[b][rp] = 0ULL;

#pragma unroll
        for (int k4 = 0; k4 < 3; k4++) {
            float4 hv[NBX];
#pragma unroll
            for (int b = 0; b < NBX; b++)
                hv[b] = *(const float4*)&s_h[b * HSTR + kbase + 4 * k4];
#pragma unroll
            for (int kk = 0; kk < 4; kk++) {
#pragma unroll
                for (int b = 0; b < NBX; b++) {
                    float hs = (kk == 0) ? hv[b].x : (kk == 1) ? hv[b].y
                             : (kk == 2) ? hv[b].z : hv[b].w;
                    unsigned long long h2 = pack2_(hs, hs);
#pragma unroll
                    for (int rp = 0; rp < 3; rp++)
                        fma2_(acc2[b][rp], h2, w2[rp][4 * k4 + kk]);
                }
            }
        }
        {
            float* pb = s_p + buf * PBUF;
#pragma unroll
            for (int rp = 0; rp < 3; rp++) {
                uint32_t qc = ((uint32_t)qg + (uint32_t)(rt * 3 + rp) * 4) & 31;
                int ra = r0 + 2 * rp;
#pragma unroll
                for (int b = 0; b < NBX; b++) {
                    float2 p = unpack2_(acc2[b][rp]);
                    float* row = pb + (b * 48 + ra) * 32;
                    row[qc]      = p.x;
                    row[32 + qc] = p.y;
                }
            }
        }
        __syncthreads();

        if (tid < NBX * NUX) {
            const float* pbase = s_p + buf * PBUF + cb * 48 * 32;
            float gate[4];
#pragma unroll
            for (int g = 0; g < 4; g++) {
                int r = g * NUX + cu;
                const float* rowp = pbase + r * 32;
                uint32_t rot = (uint32_t)((r >> 1) * 4) & 31;
                float s0 = xpre[g], s1 = 0.f;
#pragma unroll
                for (int j = 0; j < 8; j += 2) {
                    float4 v0 = *(const float4*)(rowp + ((4 * j + rot) & 31));
                    float4 v1 = *(const float4*)(rowp + ((4 * j + 4 + rot) & 31));
                    s0 += (v0.x + v0.y) + (v0.z + v0.w);
                    s1 += (v1.x + v1.y) + (v1.z + v1.w);
                }
                gate[g] = s0 + s1;
            }
            float c = sigm_(gate[1]) * s_c[tid] + sigm_(gate[0]) * tanh_(gate[2]);
            s_c[tid] = c;
            float h = sigm_(gate[3]) * tanh_(c);
            __stcg(out + ((size_t)((bb0 + cb) * S_ + tt)) * 768 + dir * H_ + u0 + cu, h);
            red_release_add(mycnt);
        }
        buf ^= 1;
    }
}

// ---------------- windowed attention ----------------
__global__ __launch_bounds__(256) void attn_kernel(
    float* __restrict__ hcat, const float* __restrict__ attnW,
    const int* __restrict__ wsp)
{
    int gw   = (int)((blockIdx.x * blockDim.x + threadIdx.x) >> 5);
    int lane = threadIdx.x & 31;
    if (gw >= M_) return;
    int b = gw >> 10, i = gw & 1023;
    int Wn = wsp ? *wsp : 32;
    if (Wn < 0) Wn = 0;
    if (Wn > S_) Wn = S_;

    const float* w2 = attnW + H_;
    const float* w3 = attnW + 2 * H_;
    const float* hi = hcat + (size_t)gw * 768;

    float v[12], a[12];
#pragma unroll
    for (int q = 0; q < 12; q++) {
        int k = q * 32 + lane;
        v[q] = w2[k] + hi[k] * w3[k];
        a[q] = 0.f;
    }
    float m = -1e30f, Z = 0.f;
    int jlo = i - Wn; if (jlo < 0) jlo = 0;
    int jhi = i + Wn; if (jhi > S_ - 1) jhi = S_ - 1;

    for (int j = jlo; j <= jhi; j++) {
        const float* hj = hcat + ((size_t)(b * S_ + j)) * 768;
        float hq[12];
        float s = 0.f;
#pragma unroll
        for (int q = 0; q < 12; q++) {
            hq[q] = hj[q * 32 + lane];
            s = fmaf(v[q], hq[q], s);
        }
#pragma unroll
        for (int o = 16; o; o >>= 1) s += __shfl_xor_sync(0xffffffffu, s, o);
        float mn = fmaxf(m, s);
        float r  = __expf(m - mn);
        float e  = __expf(s - mn);
        Z = Z * r + e;
#pragma unroll
        for (int q = 0; q < 12; q++) a[q] = a[q] * r + e * hq[q];
        m = mn;
    }
    float inv = 1.f / Z;
#pragma unroll
    for (int q = 0; q < 12; q++)
        hcat[(size_t)gw * 768 + H_ + q * 32 + lane] = a[q] * inv;
}

// ---------------- final gemv ----------------
__global__ __launch_bounds__(256) void gemv_kernel(
    const float* __restrict__ A, const float* __restrict__ w,
    const float* __restrict__ b, float* __restrict__ out)
{
    int gw   = (int)((blockIdx.x * blockDim.x + threadIdx.x) >> 5);
    int lane = threadIdx.x & 31;
    if (gw >= M_) return;
    float s = 0.f;
#pragma unroll
    for (int k = lane; k < 96; k += 32) s = fmaf(A[(size_t)gw * 96 + k], w[k], s);
#pragma unroll
    for (int o = 16; o; o >>= 1) s += __shfl_xor_sync(0xffffffffu, s, o);
    if (lane == 0) out[gw] = s + b[0];
}

// ---------------- host ----------------
static int pick_by_size(const int* sizes, int n, int want, unsigned char* used)
{
    for (int i = 0; i < n; i++) {
        if (!used[i] && sizes[i] == want) { used[i] = 1; return i; }
    }
    return -1;
}

extern "C" void kernel_launch(void* const* d_in, const int* in_sizes, int n_in,
                              void* d_out, int out_size)
{
    unsigned char used[64];
    for (int i = 0; i < 64; i++) used[i] = 0;
    int ix[24];
    ix[0]  = pick_by_size(in_sizes, n_in, 12582912, used);
    ix[1]  = pick_by_size(in_sizes, n_in, 1179648,  used);
    ix[2]  = pick_by_size(in_sizes, n_in, 589824,   used);
    ix[3]  = pick_by_size(in_sizes, n_in, 1536,     used);
    ix[4]  = pick_by_size(in_sizes, n_in, 1179648,  used);
    ix[5]  = pick_by_size(in_sizes, n_in, 589824,   used);
    ix[6]  = pick_by_size(in_sizes, n_in, 1536,     used);
    ix[7]  = pick_by_size(in_sizes, n_in, 294912,   used);
    ix[8]  = pick_by_size(in_sizes, n_in, 384,      used);
    ix[9]  = pick_by_size(in_sizes, n_in, 1152,     used);
    ix[10] = pick_by_size(in_sizes, n_in, 1,        used);
    ix[11] = pick_by_size(in_sizes, n_in, 1179648,  used);
    ix[12] = pick_by_size(in_sizes, n_in, 589824,   used);
    ix[13] = pick_by_size(in_sizes, n_in, 1536,     used);
    ix[14] = pick_by_size(in_sizes, n_in, 1179648,  used);
    ix[15] = pick_by_size(in_sizes, n_in, 589824,   used);
    ix[16] = pick_by_size(in_sizes, n_in, 1536,     used);
    ix[17] = pick_by_size(in_sizes, n_in, 98304,    used);
    ix[18] = pick_by_size(in_sizes, n_in, 256,      used);
    ix[19] = pick_by_size(in_sizes, n_in, 24576,    used);
    ix[20] = pick_by_size(in_sizes, n_in, 96,       used);
    ix[21] = pick_by_size(in_sizes, n_in, 96,       used);
    ix[22] = pick_by_size(in_sizes, n_in, 1,        used);
    ix[23] = pick_by_size(in_sizes, n_in, 1,        used);

    bool ok = true;
    for (int i = 0; i < 23; i++) if (ix[i] < 0) ok = false;
    if (!ok) {
        for (int i = 0; i < 24; i++) ix[i] = (i < n_in) ? i : -1;
    }

    const float* x      = (const float*)d_in[ix[0]];
    const float* l1Wihf = (const float*)d_in[ix[1]];
    const float* l1Whhf = (const float*)d_in[ix[2]];
    const float* l1bf   = (const float*)d_in[ix[3]];
    const float* l1Wihb = (const float*)d_in[ix[4]];
    const float* l1Whhb = (const float*)d_in[ix[5]];
    const float* l1bb   = (const float*)d_in[ix[6]];
    const float* fc1W   = (const float*)d_in[ix[7]];
    const float* fc1b   = (const float*)d_in[ix[8]];
    const float* attnW  = (const float*)d_in[ix[9]];
    const float* l2Wihf = (const float*)d_in[ix[11]];
    const float* l2Whhf = (const float*)d_in[ix[12]];
    const float* l2bf   = (const float*)d_in[ix[13]];
    const float* l2Wihb = (const float*)d_in[ix[14]];
    const float* l2Whhb = (const float*)d_in[ix[15]];
    const float* l2bb   = (const float*)d_in[ix[16]];
    const float* W1     = (const float*)d_in[ix[17]];
    const float* b1     = (const float*)d_in[ix[18]];
    const float* W2     = (const float*)d_in[ix[19]];
    const float* b2     = (const float*)d_in[ix[20]];
    const float* W3     = (const float*)d_in[ix[21]];
    const float* b3     = (const float*)d_in[ix[22]];
    const int*   wsp    = (ix[23] >= 0) ? (const int*)d_in[ix[23]] : nullptr;

    float *xpAll, *lstm, *hcat, *h2, *mlp1, *mlp2;
    __nv_bfloat16 *W2b, *Wfc;
    cudaGetSymbolAddress((void**)&xpAll, g_xpAll);
    cudaGetSymbolAddress((void**)&lstm,  g_lstm);
    cudaGetSymbolAddress((void**)&hcat,  g_hcat);
    cudaGetSymbolAddress((void**)&h2,    g_h2);
    cudaGetSymbolAddress((void**)&mlp1,  g_mlp1);
    cudaGetSymbolAddress((void**)&mlp2,  g_mlp2);
    cudaGetSymbolAddress((void**)&W2b,   g_W2);
    cudaGetSymbolAddress((void**)&Wfc,   g_Wfc);

    size_t lsm = (size_t)(NBX * HSTR + 2 * PBUF + NBX * NUX) * sizeof(float);
    cudaFuncSetAttribute(lstm_scan_kernel,
                         cudaFuncAttributeMaxDynamicSharedMemorySize, (int)lsm);
    size_t tgsm = 65536;
    cudaFuncSetAttribute(tgemm_kernel,
                         cudaFuncAttributeMaxDynamicSharedMemorySize, (int)tgsm);

    const int WPQ   = G4 * 192;
    const int FC1PQ = H_ * 192;
    dim3 xp_grid(G8 / 128, M_ / 128);       // combined xproj: 24 x 128
    dim3 fc_grid(H_ / 128, M_ / 128);       // fc1: 3 x 128

    // fc1W prepped ONCE
    split_prep_kernel<<<(FC1PQ + 255) / 256, 256>>>(fc1W, Wfc, FC1PQ, 1);

    // ---- layer 1: weight preps + ONE combined xproj GEMM (A converted in-kernel) ----
    split_prep_kernel<<<(WPQ + 255) / 256, 256>>>(l1Wihf, W2b, WPQ, 1);
    split_prep_kernel<<<(WPQ + 255) / 256, 256>>>(l1Wihb, W2b + (size_t)G4 * K2, WPQ, 1);
    tgemm_kernel<<<xp_grid, 256, tgsm>>>(x, W2b, l1bf, l1bb, 12, xpAll, G8);
    flags_zero_kernel<<<1, 128>>>();
    lstm_scan_kernel<<<NCTA, TPB, lsm>>>(xpAll, l1Whhf, l1Whhb, lstm);

    // fc1 (tensor) -> h (first half of hcat, ldc=768)
    tgemm_kernel<<<fc_grid, 256, tgsm>>>(lstm, Wfc, fc1b, fc1b, 3, hcat, 768);

    // windowed attention -> second half of hcat
    attn_kernel<<<M_ / 8, 256>>>(hcat, attnW, wsp);

    // ---- layer 2 ----
    split_prep_kernel<<<(WPQ + 255) / 256, 256>>>(l2Wihf, W2b, WPQ, 1);
    split_prep_kernel<<<(WPQ + 255) / 256, 256>>>(l2Wihb, W2b + (size_t)G4 * K2, WPQ, 1);
    tgemm_kernel<<<xp_grid, 256, tgsm>>>(hcat, W2b, l2bf, l2bb, 12, xpAll, G8);
    flags_zero_kernel<<<1, 128>>>();
    lstm_scan_kernel<<<NCTA, TPB, lsm>>>(xpAll, l2Whhf, l2Whhb, lstm);

    // fc1 again (tensor) -> h2 (ldc=384)
    tgemm_kernel<<<fc_grid, 256, tgsm>>>(lstm, Wfc, fc1b, fc1b, 3, h2, H_);

    // MLP head
    gemm_bias_kernel<1><<<dim3(2, M_ / 128), 256>>>(h2,   W1, b1, mlp1, M_, 256, H_,  256);
    gemm_bias_kernel<1><<<dim3(1, M_ / 128), 256>>>(mlp1, W2, b2, mlp2, M_, 96,  256, 96);
    gemv_kernel<<<M_ / 8, 256>>>(mlp2, W3, b3, (float*)d_out);
}

// round 17
// speedup vs baseline: 2.4948x; 1.0759x over previous
#include <cuda_runtime.h>
#include <cuda_bf16.h>
#include <cstdint>
#include <cstddef>

// Problem dims
#define B_   16
#define H_   384
#define G4   1536          // 4*H
#define G8   3072          // both dirs
#define M_   16384         // B*S
#define S_   1024
#define K2   2304          // split-GEMM K'' = 3*768

// ---------------- scratch ----------------
__device__ __align__(256) float g_xpAll [(size_t)M_ * G8];
__device__ __align__(256) float g_lstm  [(size_t)M_ * 768];
__device__ __align__(256) float g_hcat  [(size_t)M_ * 768];
__device__ __align__(256) float g_h2    [(size_t)M_ * H_];
__device__ __align__(256) float g_mlp1  [(size_t)M_ * 256];
__device__ __align__(256) float g_mlp2  [(size_t)M_ * 96];
__device__ __align__(256) __nv_bfloat16 g_A2 [(size_t)M_ * K2];
__device__ __align__(256) __nv_bfloat16 g_W2 [(size_t)G8 * K2];
__device__ __align__(256) __nv_bfloat16 g_Wfc[(size_t)H_ * K2];
__device__ __align__(256) unsigned g_cnt[128 * 8];

// ---------------- packed f32x2 helpers ----------------
__device__ __forceinline__ void fma2_(unsigned long long& d,
                                      unsigned long long a,
                                      unsigned long long b) {
    asm("fma.rn.f32x2 %0, %1, %2, %0;" : "+l"(d) : "l"(a), "l"(b));
}
__device__ __forceinline__ unsigned long long pack2_(float x, float y) {
    unsigned long long d;
    asm("mov.b64 %0, {%1, %2};" : "=l"(d) : "f"(x), "f"(y));
    return d;
}
__device__ __forceinline__ float2 unpack2_(unsigned long long v) {
    float2 r;
    asm("mov.b64 {%0, %1}, %2;" : "=f"(r.x), "=f"(r.y) : "l"(v));
    return r;
}
__device__ __forceinline__ unsigned bfhi2_(float a, float b) {
    __nv_bfloat162 t(__float2bfloat16(a), __float2bfloat16(b));
    return *(unsigned*)&t;
}
__device__ __forceinline__ unsigned bflo2_(float a, float b) {
    float ha = __bfloat162float(__float2bfloat16(a));
    float hb = __bfloat162float(__float2bfloat16(b));
    __nv_bfloat162 t(__float2bfloat16(a - ha), __float2bfloat16(b - hb));
    return *(unsigned*)&t;
}

// ---------------- generic SIMT GEMM (MLP head) ----------------
template<int ACT>
__global__ __launch_bounds__(256, 2) void gemm_bias_kernel(
    const float* __restrict__ A, const float* __restrict__ W,
    const float* __restrict__ bias, float* __restrict__ C,
    int M, int N, int K, int ldc)
{
    __shared__ float sA[16][132];
    __shared__ float sB[16][132];
    int tid = threadIdx.x;
    int m0 = blockIdx.y * 128;
    int n0 = blockIdx.x * 128;
    int tx = tid & 15, ty = tid >> 4;

    unsigned long long acc2[8][4];
#pragma unroll
    for (int i = 0; i < 8; i++)
#pragma unroll
        for (int j = 0; j < 4; j++) acc2[i][j] = 0ULL;

    for (int k0 = 0; k0 < K; k0 += 16) {
#pragma unroll
        for (int e = 0; e < 2; e++) {
            int f4 = tid + 256 * e;
            int r  = f4 >> 2;
            int c4 = (f4 & 3) << 2;
            float4 av = *(const float4*)(A + (size_t)(m0 + r) * K + k0 + c4);
            sA[c4 + 0][r] = av.x; sA[c4 + 1][r] = av.y;
            sA[c4 + 2][r] = av.z; sA[c4 + 3][r] = av.w;
            int n = n0 + r;
            float4 wv = make_float4(0.f, 0.f, 0.f, 0.f);
            if (n < N) wv = *(const float4*)(W + (size_t)n * K + k0 + c4);
            sB[c4 + 0][r] = wv.x; sB[c4 + 1][r] = wv.y;
            sB[c4 + 2][r] = wv.z; sB[c4 + 3][r] = wv.w;
        }
        __syncthreads();
#pragma unroll
        for (int kk = 0; kk < 16; kk++) {
            float a[8];
            *(float4*)&a[0] = *(const float4*)&sA[kk][ty * 8];
            *(float4*)&a[4] = *(const float4*)&sA[kk][ty * 8 + 4];
            ulonglong2 bv0 = *(const ulonglong2*)&sB[kk][tx * 8];
            ulonglong2 bv1 = *(const ulonglong2*)&sB[kk][tx * 8 + 4];
            unsigned long long b2[4] = {bv0.x, bv0.y, bv1.x, bv1.y};
#pragma unroll
            for (int i = 0; i < 8; i++) {
                unsigned long long a2 = pack2_(a[i], a[i]);
#pragma unroll
                for (int j = 0; j < 4; j++)
                    fma2_(acc2[i][j], a2, b2[j]);
            }
        }
        __syncthreads();
    }

#pragma unroll
    for (int i = 0; i < 8; i++) {
        int m = m0 + ty * 8 + i;
#pragma unroll
        for (int j2 = 0; j2 < 4; j2++) {
            float2 p = unpack2_(acc2[i][j2]);
            int n = n0 + tx * 8 + j2 * 2;
            if (n < N) {
                float v0 = p.x + bias[n];
                if (ACT) v0 = fmaxf(v0, 0.f);
                C[(size_t)m * ldc + n] = v0;
            }
            if (n + 1 < N) {
                float v1 = p.y + bias[n + 1];
                if (ACT) v1 = fmaxf(v1, 0.f);
                C[(size_t)m * ldc + n + 1] = v1;
            }
        }
    }
}

// ---------------- bf16 split prep (vectorized: 8 floats/thread, 16B stores) ----------------
// mode 0 (A): [hi | hi | lo]     mode 1 (W): [hi | lo | hi]
__global__ __launch_bounds__(256) void split_prep_kernel(
    const float* __restrict__ in, __nv_bfloat16* __restrict__ out,
    int nocts, int mode)
{
    int g = blockIdx.x * blockDim.x + threadIdx.x;
    if (g >= nocts) return;
    int m = g / 96;
    int q = (g % 96) * 8;
    const float* p = in + (size_t)m * 768 + q;
    float4 v0 = *(const float4*)p;
    float4 v1 = *(const float4*)(p + 4);
    uint4 hi, lo;
    hi.x = bfhi2_(v0.x, v0.y); hi.y = bfhi2_(v0.z, v0.w);
    hi.z = bfhi2_(v1.x, v1.y); hi.w = bfhi2_(v1.z, v1.w);
    lo.x = bflo2_(v0.x, v0.y); lo.y = bflo2_(v0.z, v0.w);
    lo.z = bflo2_(v1.x, v1.y); lo.w = bflo2_(v1.z, v1.w);
    __nv_bfloat16* o = out + (size_t)m * K2 + q;
    *(uint4*)(o) = hi;
    if (mode == 0) {
        *(uint4*)(o + 768)  = hi;
        *(uint4*)(o + 1536) = lo;
    } else {
        *(uint4*)(o + 768)  = lo;
        *(uint4*)(o + 1536) = hi;
    }
}

// ---------------- warp-MMA bf16 GEMM (R14: A via prepped A2 + cp.async) ----------------
#define TG_NBLK 36

__device__ __forceinline__ uint32_t smem_u32_(const void* p) {
    uint32_t a;
    asm("{ .reg .u64 t; cvta.to.shared.u64 t, %1; cvt.u32.u64 %0, t; }" : "=r"(a) : "l"(p));
    return a;
}
__device__ __forceinline__ uint32_t swz_(uint32_t off) {
    return off ^ ((off >> 3) & 0x70);
}
__device__ __forceinline__ void cp16_(uint32_t s, const void* g) {
    asm volatile("cp.async.cg.shared.global [%0], [%1], 16;" :: "r"(s), "l"(g) : "memory");
}
#define LDSM4_(d0, d1, d2, d3, addr) \
    asm volatile("ldmatrix.sync.aligned.m8n8.x4.shared.b16 {%0,%1,%2,%3}, [%4];" \
                 : "=r"(d0), "=r"(d1), "=r"(d2), "=r"(d3) : "r"(addr))
#define MMA16816_(c, a, b0, b1) \
    asm volatile("mma.sync.aligned.m16n8k16.row.col.f32.bf16.bf16.f32 " \
                 "{%0,%1,%2,%3}, {%4,%5,%6,%7}, {%8,%9}, {%0,%1,%2,%3};" \
                 : "+f"((c)[0]), "+f"((c)[1]), "+f"((c)[2]), "+f"((c)[3]) \
                 : "r"((a)[0]), "r"((a)[1]), "r"((a)[2]), "r"((a)[3]), \
                   "r"(b0), "r"(b1))

__global__ __launch_bounds__(256) void tgemm_kernel(
    const __nv_bfloat16* __restrict__ A2,
    const __nv_bfloat16* __restrict__ W2,
    const float* __restrict__ biasA,
    const float* __restrict__ biasB,
    int nsplit,
    float* __restrict__ C, int ldc)
{
    extern __shared__ char smraw[];
    uint32_t sb = smem_u32_(smraw);
    int tid  = threadIdx.x;
    int wid  = tid >> 5;
    int lane = tid & 31;
    int n0 = blockIdx.x * 128;
    int m0 = blockIdx.y * 128;
    int wm = (wid & 3) * 32;
    int wn = (wid >> 2) * 64;

    const float* bp = ((int)blockIdx.x < nsplit) ? biasA : biasB;
    int coff = ((int)blockIdx.x < nsplit) ? 0 : nsplit * 128;

    float acc[2][8][4];
#pragma unroll
    for (int mt = 0; mt < 2; mt++)
#pragma unroll
        for (int nt = 0; nt < 8; nt++)
#pragma unroll
            for (int e = 0; e < 4; e++) acc[mt][nt][e] = 0.f;

    int arow = wm + (lane & 15);
    uint32_t arowoff = (uint32_t)arow * 128;
    uint32_t amask   = (uint32_t)(arow & 7) << 4;
    uint32_t akh     = (uint32_t)(lane >> 4) * 16;

    int brow = wn + (lane & 7) + ((lane >> 4) << 3);
    uint32_t browoff = (uint32_t)brow * 128;
    uint32_t bmask   = (uint32_t)(brow & 7) << 4;
    uint32_t bkh     = (uint32_t)((lane >> 3) & 1) * 16;

#pragma unroll
    for (int i = 0; i < 4; i++) {
        int cid = tid + 256 * i;
        int row = cid >> 3, ch = cid & 7;
        uint32_t so = swz_((uint32_t)row * 128 + (uint32_t)ch * 16);
        cp16_(sb + so,           A2 + (size_t)(m0 + row) * K2 + ch * 8);
        cp16_(sb + 32768 + so,   W2 + (size_t)(n0 + row) * K2 + ch * 8);
    }
    asm volatile("cp.async.commit_group;" ::: "memory");

    for (int blk = 0; blk < TG_NBLK; blk++) {
        int bufc = blk & 1;
        if (blk + 1 < TG_NBLK) {
            int bufn = (blk + 1) & 1;
            size_t gk = (size_t)(blk + 1) * 64;
#pragma unroll
            for (int i = 0; i < 4; i++) {
                int cid = tid + 256 * i;
                int row = cid >> 3, ch = cid & 7;
                uint32_t so = swz_((uint32_t)row * 128 + (uint32_t)ch * 16);
                cp16_(sb + bufn * 16384 + so,
                      A2 + (size_t)(m0 + row) * K2 + gk + ch * 8);
                cp16_(sb + 32768 + bufn * 16384 + so,
                      W2 + (size_t)(n0 + row) * K2 + gk + ch * 8);
            }
            asm volatile("cp.async.commit_group;" ::: "memory");
            asm volatile("cp.async.wait_group 1;" ::: "memory");
        } else {
            asm volatile("cp.async.wait_group 0;" ::: "memory");
        }
        __syncthreads();

        uint32_t abuf = sb + bufc * 16384;
        uint32_t bbuf = sb + 32768 + bufc * 16384;
#pragma unroll
        for (int kk = 0; kk < 4; kk++) {
            uint32_t acol = (akh + (uint32_t)kk * 32) ^ amask;
            uint32_t bcol = (bkh + (uint32_t)kk * 32) ^ bmask;
            uint32_t a[2][4], b[4][4];
#pragma unroll
            for (int mt = 0; mt < 2; mt++)
                LDSM4_(a[mt][0], a[mt][1], a[mt][2], a[mt][3],
                       abuf + arowoff + mt * 2048 + acol);
#pragma unroll
            for (int g = 0; g < 4; g++)
                LDSM4_(b[g][0], b[g][1], b[g][2], b[g][3],
                       bbuf + browoff + g * 2048 + bcol);
#pragma unroll
            for (int mt = 0; mt < 2; mt++)
#pragma unroll
                for (int nt = 0; nt < 8; nt++) {
                    int g = nt >> 1, h = (nt & 1) * 2;
                    MMA16816_(acc[mt][nt], a[mt], b[g][h], b[g][h + 1]);
                }
        }
        __syncthreads();
    }

#pragma unroll
    for (int mt = 0; mt < 2; mt++)
#pragma unroll
        for (int nt = 0; nt < 8; nt++) {
            int row = m0 + wm + mt * 16 + (lane >> 2);
            int col = n0 + wn + nt * 8 + (lane & 3) * 2;
            float2 bv = *(const float2*)(bp + (col - coff));
            float2 o0 = make_float2(acc[mt][nt][0] + bv.x, acc[mt][nt][1] + bv.y);
            float2 o1 = make_float2(acc[mt][nt][2] + bv.x, acc[mt][nt][3] + bv.y);
            *(float2*)(C + (size_t)row * ldc + col) = o0;
            *(float2*)(C + (size_t)(row + 8) * ldc + col) = o1;
        }
}

// ---------------- LSTM recurrent scan (R12/R14: warp-autonomous, Whh in regs) ----------------
#define NUX   12
#define NBX   8
#define HSTR  392
#define PBUF  (NBX * 48 * 32)
#define NCTA  128
#define TPB   256

__device__ __forceinline__ float sigm_(float x) { return 1.f / (1.f + __expf(-x)); }
__device__ __forceinline__ float tanh_(float x) {
    float t = __expf(-2.f * fabsf(x));
    float r = (1.f - t) / (1.f + t);
    return x < 0.f ? -r : r;
}
__device__ __forceinline__ void red_release_add(unsigned* p) {
    asm volatile("red.release.gpu.global.add.u32 [%0], %1;" :: "l"(p), "r"(1u) : "memory");
}
__device__ __forceinline__ unsigned ld_relaxed(const unsigned* p) {
    unsigned v;
    asm volatile("ld.relaxed.gpu.global.u32 %0, [%1];" : "=r"(v) : "l"(p) : "memory");
    return v;
}

__global__ void flags_zero_kernel()
{
    g_cnt[threadIdx.x * 8] = 0u;
}

__global__ __launch_bounds__(TPB, 1) void lstm_scan_kernel(
    const float* __restrict__ xpAll,   // [M][3072], dir offset 1536
    const float* __restrict__ WhhF, const float* __restrict__ WhhB,
    float* __restrict__ out)
{
    extern __shared__ float sm[];
    float* s_h = sm;
    float* s_p = s_h + NBX * HSTR;
    float* s_c = s_p + 2 * PBUF;

    int tid  = threadIdx.x;
    int wrp  = tid >> 5;
    int lane = tid & 31;
    int dir = blockIdx.x >> 6;
    int bg  = (blockIdx.x >> 5) & 1;
    int ug  = blockIdx.x & 31;
    int u0  = ug * NUX;
    int bb0 = bg * NBX;
    int clique = dir * 2 + bg;
    const float* Whh = dir ? WhhB : WhhF;

    int ql    = lane & 3;
    int rt    = lane >> 2;
    int kbase = wrp * 48 + ql * 12;
    int r0    = rt * 6;
    int qg    = wrp * 4 + ql;

    unsigned long long w2[3][12];
#pragma unroll
    for (int rp = 0; rp < 3; rp++) {
        int ra = r0 + 2 * rp, rb = ra + 1;
        const float* Wa = Whh + (size_t)((ra / NUX) * H_ + u0 + (ra % NUX)) * H_ + kbase;
        const float* Wb = Whh + (size_t)((rb / NUX) * H_ + u0 + (rb % NUX)) * H_ + kbase;
#pragma unroll
        for (int k = 0; k < 12; k++)
            w2[rp][k] = pack2_(__ldg(Wa + k), __ldg(Wb + k));
    }
    if (tid < NBX * NUX) s_c[tid] = 0.f;

    {
        int kw = wrp * 48;
#pragma unroll
        for (int e = 0; e < 3; e++) {
            int idx = lane + 32 * e;
            int b   = idx / 12;
            int c4  = (idx % 12) * 4;
            *(float4*)&s_h[b * HSTR + kw + c4] = make_float4(0.f, 0.f, 0.f, 0.f);
        }
    }
    __syncthreads();

    unsigned* mycnt = &g_cnt[(clique * 32 + ug) * 8];
    int cb = tid / NUX, cu = tid % NUX;
    int buf = 0;

    for (int step = 0; step < S_; step++) {
        int tt = dir ? (S_ - 1 - step) : step;

        float xpre[4] = {0.f, 0.f, 0.f, 0.f};
        if (tid < NBX * NUX) {
            size_t base = ((size_t)((bb0 + cb) * S_ + tt)) * G8 + (size_t)dir * G4 + u0 + cu;
#pragma unroll
            for (int g = 0; g < 4; g++) xpre[g] = __ldg(xpAll + base + g * H_);
        }

        if (step > 0) {
            unsigned target = 96u * (unsigned)step;
            if (lane < 4) {
                const unsigned* f = &g_cnt[(clique * 32 + (wrp << 2) + lane) * 8];
                while (ld_relaxed(f) < target) { }
            }
            __syncwarp();
            asm volatile("fence.acq_rel.gpu;" ::: "memory");
            int tp = dir ? (tt + 1) : (tt - 1);
            int kw = wrp * 48;
#pragma unroll
            for (int e = 0; e < 3; e++) {
                int idx = lane + 32 * e;
                int b   = idx / 12;
                int c4  = (idx % 12) * 4;
                int k   = kw + c4;
                const float4* src = (const float4*)(out +
                    ((size_t)((bb0 + b) * S_ + tp)) * 768 + dir * H_ + k);
                *(float4*)&s_h[b * HSTR + k] = __ldcg(src);
            }
            __syncwarp();
        }

        unsigned long long acc2[NBX][3];
#pragma unroll
        for (int b = 0; b < NBX; b++)
#pragma unroll
            for (int rp = 0; rp < 3; rp++) acc2[b][rp] = 0ULL;

#pragma unroll
        for (int k4 = 0; k4 < 3; k4++) {
            float4 hv[NBX];
#pragma unroll
            for (int b = 0; b < NBX; b++)
                hv[b] = *(const float4*)&s_h[b * HSTR + kbase + 4 * k4];
#pragma unroll
            for (int kk = 0; kk < 4; kk++) {
#pragma unroll
                for (int b = 0; b < NBX; b++) {
                    float hs = (kk == 0) ? hv[b].x : (kk == 1) ? hv[b].y
                             : (kk == 2) ? hv[b].z : hv[b].w;
                    unsigned long long h2 = pack2_(hs, hs);
#pragma unroll
                    for (int rp = 0; rp < 3; rp++)
                        fma2_(acc2[b][rp], h2, w2[rp][4 * k4 + kk]);
                }
            }
        }
        {
            float* pb = s_p + buf * PBUF;
#pragma unroll
            for (int rp = 0; rp < 3; rp++) {
                uint32_t qc = ((uint32_t)qg + (uint32_t)(rt * 3 + rp) * 4) & 31;
                int ra = r0 + 2 * rp;
#pragma unroll
                for (int b = 0; b < NBX; b++) {
                    float2 p = unpack2_(acc2[b][rp]);
                    float* row = pb + (b * 48 + ra) * 32;
                    row[qc]      = p.x;
                    row[32 + qc] = p.y;
                }
            }
        }
        __syncthreads();

        if (tid < NBX * NUX) {
            const float* pbase = s_p + buf * PBUF + cb * 48 * 32;
            float gate[4];
#pragma unroll
            for (int g = 0; g < 4; g++) {
                int r = g * NUX + cu;
                const float* rowp = pbase + r * 32;
                uint32_t rot = (uint32_t)((r >> 1) * 4) & 31;
                float s0 = xpre[g], s1 = 0.f;
#pragma unroll
                for (int j = 0; j < 8; j += 2) {
                    float4 v0 = *(const float4*)(rowp + ((4 * j + rot) & 31));
                    float4 v1 = *(const float4*)(rowp + ((4 * j + 4 + rot) & 31));
                    s0 += (v0.x + v0.y) + (v0.z + v0.w);
                    s1 += (v1.x + v1.y) + (v1.z + v1.w);
                }
                gate[g] = s0 + s1;
            }
            float c = sigm_(gate[1]) * s_c[tid] + sigm_(gate[0]) * tanh_(gate[2]);
            s_c[tid] = c;
            float h = sigm_(gate[3]) * tanh_(c);
            __stcg(out + ((size_t)((bb0 + cb) * S_ + tt)) * 768 + dir * H_ + u0 + cu, h);
            red_release_add(mycnt);
        }
        buf ^= 1;
    }
}

// ---------------- windowed attention ----------------
__global__ __launch_bounds__(256) void attn_kernel(
    float* __restrict__ hcat, const float* __restrict__ attnW,
    const int* __restrict__ wsp)
{
    int gw   = (int)((blockIdx.x * blockDim.x + threadIdx.x) >> 5);
    int lane = threadIdx.x & 31;
    if (gw >= M_) return;
    int b = gw >> 10, i = gw & 1023;
    int Wn = wsp ? *wsp : 32;
    if (Wn < 0) Wn = 0;
    if (Wn > S_) Wn = S_;

    const float* w2 = attnW + H_;
    const float* w3 = attnW + 2 * H_;
    const float* hi = hcat + (size_t)gw * 768;

    float v[12], a[12];
#pragma unroll
    for (int q = 0; q < 12; q++) {
        int k = q * 32 + lane;
        v[q] = w2[k] + hi[k] * w3[k];
        a[q] = 0.f;
    }
    float m = -1e30f, Z = 0.f;
    int jlo = i - Wn; if (jlo < 0) jlo = 0;
    int jhi = i + Wn; if (jhi > S_ - 1) jhi = S_ - 1;

    for (int j = jlo; j <= jhi; j++) {
        const float* hj = hcat + ((size_t)(b * S_ + j)) * 768;
        float hq[12];
        float s = 0.f;
#pragma unroll
        for (int q = 0; q < 12; q++) {
            hq[q] = hj[q * 32 + lane];
            s = fmaf(v[q], hq[q], s);
        }
#pragma unroll
        for (int o = 16; o; o >>= 1) s += __shfl_xor_sync(0xffffffffu, s, o);
        float mn = fmaxf(m, s);
        float r  = __expf(m - mn);
        float e  = __expf(s - mn);
        Z = Z * r + e;
#pragma unroll
        for (int q = 0; q < 12; q++) a[q] = a[q] * r + e * hq[q];
        m = mn;
    }
    float inv = 1.f / Z;
#pragma unroll
    for (int q = 0; q < 12; q++)
        hcat[(size_t)gw * 768 + H_ + q * 32 + lane] = a[q] * inv;
}

// ---------------- final gemv ----------------
__global__ __launch_bounds__(256) void gemv_kernel(
    const float* __restrict__ A, const float* __restrict__ w,
    const float* __restrict__ b, float* __restrict__ out)
{
    int gw   = (int)((blockIdx.x * blockDim.x + threadIdx.x) >> 5);
    int lane = threadIdx.x & 31;
    if (gw >= M_) return;
    float s = 0.f;
#pragma unroll
    for (int k = lane; k < 96; k += 32) s = fmaf(A[(size_t)gw * 96 + k], w[k], s);
#pragma unroll
    for (int o = 16; o; o >>= 1) s += __shfl_xor_sync(0xffffffffu, s, o);
    if (lane == 0) out[gw] = s + b[0];
}

// ---------------- host ----------------
static int pick_by_size(const int* sizes, int n, int want, unsigned char* used)
{
    for (int i = 0; i < n; i++) {
        if (!used[i] && sizes[i] == want) { used[i] = 1; return i; }
    }
    return -1;
}

extern "C" void kernel_launch(void* const* d_in, const int* in_sizes, int n_in,
                              void* d_out, int out_size)
{
    unsigned char used[64];
    for (int i = 0; i < 64; i++) used[i] = 0;
    int ix[24];
    ix[0]  = pick_by_size(in_sizes, n_in, 12582912, used);
    ix[1]  = pick_by_size(in_sizes, n_in, 1179648,  used);
    ix[2]  = pick_by_size(in_sizes, n_in, 589824,   used);
    ix[3]  = pick_by_size(in_sizes, n_in, 1536,     used);
    ix[4]  = pick_by_size(in_sizes, n_in, 1179648,  used);
    ix[5]  = pick_by_size(in_sizes, n_in, 589824,   used);
    ix[6]  = pick_by_size(in_sizes, n_in, 1536,     used);
    ix[7]  = pick_by_size(in_sizes, n_in, 294912,   used);
    ix[8]  = pick_by_size(in_sizes, n_in, 384,      used);
    ix[9]  = pick_by_size(in_sizes, n_in, 1152,     used);
    ix[10] = pick_by_size(in_sizes, n_in, 1,        used);
    ix[11] = pick_by_size(in_sizes, n_in, 1179648,  used);
    ix[12] = pick_by_size(in_sizes, n_in, 589824,   used);
    ix[13] = pick_by_size(in_sizes, n_in, 1536,     used);
    ix[14] = pick_by_size(in_sizes, n_in, 1179648,  used);
    ix[15] = pick_by_size(in_sizes, n_in, 589824,   used);
    ix[16] = pick_by_size(in_sizes, n_in, 1536,     used);
    ix[17] = pick_by_size(in_sizes, n_in, 98304,    used);
    ix[18] = pick_by_size(in_sizes, n_in, 256,      used);
    ix[19] = pick_by_size(in_sizes, n_in, 24576,    used);
    ix[20] = pick_by_size(in_sizes, n_in, 96,       used);
    ix[21] = pick_by_size(in_sizes, n_in, 96,       used);
    ix[22] = pick_by_size(in_sizes, n_in, 1,        used);
    ix[23] = pick_by_size(in_sizes, n_in, 1,        used);

    bool ok = true;
    for (int i = 0; i < 23; i++) if (ix[i] < 0) ok = false;
    if (!ok) {
        for (int i = 0; i < 24; i++) ix[i] = (i < n_in) ? i : -1;
    }

    const float* x      = (const float*)d_in[ix[0]];
    const float* l1Wihf = (const float*)d_in[ix[1]];
    const float* l1Whhf = (const float*)d_in[ix[2]];
    const float* l1bf   = (const float*)d_in[ix[3]];
    const float* l1Wihb = (const float*)d_in[ix[4]];
    const float* l1Whhb = (const float*)d_in[ix[5]];
    const float* l1bb   = (const float*)d_in[ix[6]];
    const float* fc1W   = (const float*)d_in[ix[7]];
    const float* fc1b   = (const float*)d_in[ix[8]];
    const float* attnW  = (const float*)d_in[ix[9]];
    const float* l2Wihf = (const float*)d_in[ix[11]];
    const float* l2Whhf = (const float*)d_in[ix[12]];
    const float* l2bf   = (const float*)d_in[ix[13]];
    const float* l2Wihb = (const float*)d_in[ix[14]];
    const float* l2Whhb = (const float*)d_in[ix[15]];
    const float* l2bb   = (const float*)d_in[ix[16]];
    const float* W1     = (const float*)d_in[ix[17]];
    const float* b1     = (const float*)d_in[ix[18]];
    const float* W2     = (const float*)d_in[ix[19]];
    const float* b2     = (const float*)d_in[ix[20]];
    const float* W3     = (const float*)d_in[ix[21]];
    const float* b3     = (const float*)d_in[ix[22]];
    const int*   wsp    = (ix[23] >= 0) ? (const int*)d_in[ix[23]] : nullptr;

    float *xpAll, *lstm, *hcat, *h2, *mlp1, *mlp2;
    __nv_bfloat16 *A2, *W2b, *Wfc;
    cudaGetSymbolAddress((void**)&xpAll, g_xpAll);
    cudaGetSymbolAddress((void**)&lstm,  g_lstm);
    cudaGetSymbolAddress((void**)&hcat,  g_hcat);
    cudaGetSymbolAddress((void**)&h2,    g_h2);
    cudaGetSymbolAddress((void**)&mlp1,  g_mlp1);
    cudaGetSymbolAddress((void**)&mlp2,  g_mlp2);
    cudaGetSymbolAddress((void**)&A2,    g_A2);
    cudaGetSymbolAddress((void**)&W2b,   g_W2);
    cudaGetSymbolAddress((void**)&Wfc,   g_Wfc);

    size_t lsm = (size_t)(NBX * HSTR + 2 * PBUF + NBX * NUX) * sizeof(float);
    cudaFuncSetAttribute(lstm_scan_kernel,
                         cudaFuncAttributeMaxDynamicSharedMemorySize, (int)lsm);
    size_t tgsm = 65536;
    cudaFuncSetAttribute(tgemm_kernel,
                         cudaFuncAttributeMaxDynamicSharedMemorySize, (int)tgsm);

    const int AOC   = M_ * 96;     // A-prep octs (8 floats each)
    const int WOC   = G4 * 96;     // W-prep octs
    const int FC1OC = H_ * 96;     // fc1W-prep octs
    dim3 xp_grid(G8 / 128, M_ / 128);       // combined xproj: 24 x 128
    dim3 fc_grid(H_ / 128, M_ / 128);       // fc1: 3 x 128

    // fc1W prepped ONCE
    split_prep_kernel<<<(FC1OC + 255) / 256, 256>>>(fc1W, Wfc, FC1OC, 1);

    // ---- layer 1: A prep + both weight preps + ONE combined xproj GEMM ----
    split_prep_kernel<<<(AOC + 255) / 256, 256>>>(x, A2, AOC, 0);
    split_prep_kernel<<<(WOC + 255) / 256, 256>>>(l1Wihf, W2b, WOC, 1);
    split_prep_kernel<<<(WOC + 255) / 256, 256>>>(l1Wihb, W2b + (size_t)G4 * K2, WOC, 1);
    tgemm_kernel<<<xp_grid, 256, tgsm>>>(A2, W2b, l1bf, l1bb, 12, xpAll, G8);
    flags_zero_kernel<<<1, 128>>>();
    lstm_scan_kernel<<<NCTA, TPB, lsm>>>(xpAll, l1Whhf, l1Whhb, lstm);

    // fc1 (tensor) -> h (first half of hcat, ldc=768)
    split_prep_kernel<<<(AOC + 255) / 256, 256>>>(lstm, A2, AOC, 0);
    tgemm_kernel<<<fc_grid, 256, tgsm>>>(A2, Wfc, fc1b, fc1b, 3, hcat, 768);

    // windowed attention -> second half of hcat
    attn_kernel<<<M_ / 8, 256>>>(hcat, attnW, wsp);

    // ---- layer 2 ----
    split_prep_kernel<<<(AOC + 255) / 256, 256>>>(hcat, A2, AOC, 0);
    split_prep_kernel<<<(WOC + 255) / 256, 256>>>(l2Wihf, W2b, WOC, 1);
    split_prep_kernel<<<(WOC + 255) / 256, 256>>>(l2Wihb, W2b + (size_t)G4 * K2, WOC, 1);
    tgemm_kernel<<<xp_grid, 256, tgsm>>>(A2, W2b, l2bf, l2bb, 12, xpAll, G8);
    flags_zero_kernel<<<1, 128>>>();
    lstm_scan_kernel<<<NCTA, TPB, lsm>>>(xpAll, l2Whhf, l2Whhb, lstm);

    // fc1 again (tensor) -> h2 (ldc=384)
    split_prep_kernel<<<(AOC + 255) / 256, 256>>>(lstm, A2, AOC, 0);
    tgemm_kernel<<<fc_grid, 256, tgsm>>>(A2, Wfc, fc1b, fc1b, 3, h2, H_);

    // MLP head
    gemm_bias_kernel<1><<<dim3(2, M_ / 128), 256>>>(h2,   W1, b1, mlp1, M_, 256, H_,  256);
    gemm_bias_kernel<1><<<dim3(1, M_ / 128), 256>>>(mlp1, W2, b2, mlp2, M_, 96,  256, 96);
    gemv_kernel<<<M_ / 8, 256>>>(mlp2, W3, b3, (float*)d_out);
}